// round 10
// baseline (speedup 1.0000x reference)
#include <cuda_runtime.h>
#include <cuda_fp16.h>
#include <math.h>
#include <cstdint>

// ---------------------------------------------------------------------------
// Problem constants
// ---------------------------------------------------------------------------
#define TOKENS 4096        // B*S = 2*2048
#define DMODEL 1024
#define DFF    4096
#define NHEADS 16
#define DK     64
#define SEQ    2048

// ---------------------------------------------------------------------------
// Scratch (device globals)
// ---------------------------------------------------------------------------
__device__ __half hx   [TOKENS * DMODEL];
__device__ __half hWq  [DMODEL * DMODEL];
__device__ __half hWk  [DMODEL * DMODEL];
__device__ __half hWv  [DMODEL * DMODEL];
__device__ __half hWo  [DMODEL * DMODEL];
__device__ __half hW1  [DFF * DMODEL];
__device__ __half hW2  [DMODEL * DFF];
__device__ __half hq   [TOKENS * DMODEL];   // pre-scaled by 1/8
__device__ __half hk   [TOKENS * DMODEL];
__device__ __half hvt  [TOKENS * DMODEL];   // V transposed: [b][h][d][s]
__device__ __half hattn[TOKENS * DMODEL];
__device__ __half hx1  [TOKENS * DMODEL];
__device__ __half hff  [TOKENS * DFF];
__device__ float  g_proj[TOKENS * DMODEL];
__device__ float  g_x1 [TOKENS * DMODEL];

// ---------------------------------------------------------------------------
// Helpers
// ---------------------------------------------------------------------------
__device__ __forceinline__ uint32_t smem_u32(const void* p) {
    uint32_t a;
    asm("{ .reg .u64 t; cvta.to.shared.u64 t, %1; cvt.u32.u64 %0, t; }"
        : "=r"(a) : "l"(p));
    return a;
}

#define CP_ASYNC16(dst_u32, src_ptr) \
    asm volatile("cp.async.cg.shared.global [%0], [%1], 16;" \
        :: "r"(dst_u32), "l"(src_ptr))
#define CP_COMMIT() asm volatile("cp.async.commit_group;")
#define CP_WAIT(n)  asm volatile("cp.async.wait_group %0;" :: "n"(n))

#define MMA_F16(c, a0, a1, a2, a3, b0, b1) \
    asm volatile("mma.sync.aligned.m16n8k16.row.col.f32.f16.f16.f32 " \
        "{%0,%1,%2,%3}, {%4,%5,%6,%7}, {%8,%9}, {%0,%1,%2,%3};" \
        : "+f"((c)[0]), "+f"((c)[1]), "+f"((c)[2]), "+f"((c)[3]) \
        : "r"(a0), "r"(a1), "r"(a2), "r"(a3), "r"(b0), "r"(b1))

#define LDSM4(r, addr) \
    asm volatile("ldmatrix.sync.aligned.m8n8.x4.shared.b16 {%0,%1,%2,%3}, [%4];" \
        : "=r"((r)[0]), "=r"((r)[1]), "=r"((r)[2]), "=r"((r)[3]) : "r"(addr))

__device__ __forceinline__ uint32_t pack_h2(float lo, float hi) {
    __half2 h = __floats2half2_rn(lo, hi);
    return *reinterpret_cast<uint32_t*>(&h);
}

// ---------------------------------------------------------------------------
// fp32 -> fp16 conversion, all tensors in one launch (grid.y selects tensor)
// ---------------------------------------------------------------------------
__global__ __launch_bounds__(256)
void f2h_all(const float* x,  __half* dx,
             const float* w0, __half* d0, const float* w1, __half* d1,
             const float* w2, __half* d2, const float* w3, __half* d3,
             const float* w4, __half* d4, const float* w5, __half* d5)
{
    const float* src; __half* dst; int n;
    switch (blockIdx.y) {
        case 0: src = x;  dst = dx; n = TOKENS * DMODEL; break;
        case 1: src = w0; dst = d0; n = DMODEL * DMODEL; break;
        case 2: src = w1; dst = d1; n = DMODEL * DMODEL; break;
        case 3: src = w2; dst = d2; n = DMODEL * DMODEL; break;
        case 4: src = w3; dst = d3; n = DMODEL * DMODEL; break;
        case 5: src = w4; dst = d4; n = DFF * DMODEL;    break;
        default:src = w5; dst = d5; n = DMODEL * DFF;    break;
    }
    int i = (blockIdx.x * 256 + threadIdx.x) * 4;
    if (i < n) {
        float4 v = *(const float4*)(src + i);
        *(__half2*)(dst + i)     = __floats2half2_rn(v.x, v.y);
        *(__half2*)(dst + i + 2) = __floats2half2_rn(v.z, v.w);
    }
}

// ---------------------------------------------------------------------------
// 128(M) x 256(N) x BK=64 fp16 GEMM, 4-stage cp.async, 1 CTA/SM,
// single-barrier multistage mainloop; 8 warps (2m x 4n), warp tile 64x64.
// smem: 4 stages x (128+256) x 72 halves = 216 KB.
// ---------------------------------------------------------------------------
#define HSTR   72
#define ATILE  (128 * HSTR)
#define BTILE  (256 * HSTR)
#define NSTAGE 4
#define GEMM_SMEM (NSTAGE * (ATILE + BTILE) * 2)   // 221184 B

#define GEMM_IDS \
    const int tid = threadIdx.x; \
    const int wid = tid >> 5; \
    const int lid = tid & 31; \
    const int gid = lid >> 2; \
    const int tig = lid & 3; \
    const int wm0 = (wid & 1) * 64; \
    const int wn0 = (wid >> 1) * 64; \
    const int ldRow = tid >> 3; \
    const int ldC8  = (tid & 7) << 3; \
    const int a_moff = (lid & 7) + ((lid >> 3) & 1) * 8; \
    const int a_koff = (lid >> 4) * 8; \
    const int b_noff = (lid & 7) + ((lid >> 4) & 1) * 8; \
    const int b_koff = ((lid >> 3) & 1) * 8;

#define GEMM_SMEM_PTRS \
    extern __shared__ __half hsm[]; \
    uint32_t sA_u[NSTAGE], sB_u[NSTAGE]; \
    _Pragma("unroll") \
    for (int s_ = 0; s_ < NSTAGE; s_++) { \
        sA_u[s_] = smem_u32(hsm + s_ * ATILE); \
        sB_u[s_] = smem_u32(hsm + NSTAGE * ATILE + s_ * BTILE); \
    }

#define GEMM_LOAD_TILE(kt, buf, Ab, Bb, K) do { \
    const __half* Ak_ = (Ab) + (size_t)(kt) * 64; \
    const __half* Bk_ = (Bb) + (size_t)(kt) * 64; \
    _Pragma("unroll") \
    for (int it = 0; it < 4; it++) { \
        int row = ldRow + it * 32; \
        CP_ASYNC16(sA_u[buf] + (uint32_t)(row * HSTR + ldC8) * 2u, \
                   Ak_ + (size_t)row * (K) + ldC8); \
    } \
    _Pragma("unroll") \
    for (int it = 0; it < 8; it++) { \
        int row = ldRow + it * 32; \
        CP_ASYNC16(sB_u[buf] + (uint32_t)(row * HSTR + ldC8) * 2u, \
                   Bk_ + (size_t)row * (K) + ldC8); \
    } \
    CP_COMMIT(); \
} while (0)

#define GEMM_COMPUTE_TILE(buf, acc) do { \
    const uint32_t aB_ = sA_u[buf] + (uint32_t)((wm0 + a_moff) * HSTR + a_koff) * 2u; \
    const uint32_t bB_ = sB_u[buf] + (uint32_t)((wn0 + b_noff) * HSTR + b_koff) * 2u; \
    _Pragma("unroll") \
    for (int ks = 0; ks < 4; ks++) { \
        uint32_t a[4][4], b[4][4]; \
        _Pragma("unroll") \
        for (int fm = 0; fm < 4; fm++) \
            LDSM4(a[fm], aB_ + (uint32_t)(fm * 16 * HSTR) * 2u + ks * 32); \
        _Pragma("unroll") \
        for (int fn2 = 0; fn2 < 4; fn2++) \
            LDSM4(b[fn2], bB_ + (uint32_t)(fn2 * 16 * HSTR) * 2u + ks * 32); \
        _Pragma("unroll") \
        for (int fm = 0; fm < 4; fm++) \
            _Pragma("unroll") \
            for (int fn = 0; fn < 8; fn++) \
                MMA_F16(acc[fm][fn], \
                        a[fm][0], a[fm][1], a[fm][2], a[fm][3], \
                        b[fn >> 1][(fn & 1) * 2], b[fn >> 1][(fn & 1) * 2 + 1]); \
    } \
} while (0)

// Single-barrier 4-stage: wait(kt) -> barrier -> compute(kt) -> load(kt+3).
// Stage (kt+3)%4 == (kt-1)%4 was last read in iter kt-1; barrier at top of
// iter kt guarantees all warps finished that compute.
#define GEMM_MAINLOOP(Ab, Bb, K, acc) do { \
    const int KT_ = (K) >> 6; \
    GEMM_LOAD_TILE(0, 0, Ab, Bb, K); \
    GEMM_LOAD_TILE(1, 1, Ab, Bb, K); \
    GEMM_LOAD_TILE(2, 2, Ab, Bb, K); \
    for (int kt = 0; kt < KT_; kt++) { \
        if (kt + 2 < KT_)      { CP_WAIT(2); } \
        else if (kt + 1 < KT_) { CP_WAIT(1); } \
        else                   { CP_WAIT(0); } \
        __syncthreads(); \
        GEMM_COMPUTE_TILE(kt % NSTAGE, acc); \
        if (kt + 3 < KT_) GEMM_LOAD_TILE(kt + 3, (kt + 3) % NSTAGE, Ab, Bb, K); \
    } \
} while (0)

// ---------------------------------------------------------------------------
// General GEMM:  C[M,N] = A[M,K] @ B[N,K]^T
// EPI: 0 = fp16, 3 = exact GELU -> fp16, 4 = fp32
// ---------------------------------------------------------------------------
template <int EPI>
__global__ __launch_bounds__(256, 1)
void gemm256(const __half* __restrict__ A, const __half* __restrict__ B,
             void* __restrict__ Cv, int M, int N, int K)
{
    GEMM_SMEM_PTRS
    GEMM_IDS
    const int bm = blockIdx.y * 128;
    const int bn = blockIdx.x * 256;

    const __half* Ab = A + (size_t)bm * K;
    const __half* Bb = B + (size_t)bn * K;

    float acc[4][8][4];
#pragma unroll
    for (int i = 0; i < 4; i++)
#pragma unroll
        for (int j = 0; j < 8; j++)
#pragma unroll
            for (int r = 0; r < 4; r++) acc[i][j][r] = 0.f;

    GEMM_MAINLOOP(Ab, Bb, K, acc);

#pragma unroll
    for (int fm = 0; fm < 4; fm++) {
#pragma unroll
        for (int fn = 0; fn < 8; fn++) {
            float v[4];
#pragma unroll
            for (int r = 0; r < 4; r++) {
                float t = acc[fm][fn][r];
                if (EPI == 3) t = 0.5f * t * (1.f + erff(t * 0.70710678118654752f));
                v[r] = t;
            }
            const int row0 = bm + wm0 + fm * 16 + gid;
            const int col  = bn + wn0 + fn * 8 + tig * 2;
            if (EPI == 4) {
                float* C = (float*)Cv;
                *(float2*)(C + (size_t)row0 * N + col)       = make_float2(v[0], v[1]);
                *(float2*)(C + (size_t)(row0 + 8) * N + col) = make_float2(v[2], v[3]);
            } else {
                __half* C = (__half*)Cv;
                *(__half2*)(C + (size_t)row0 * N + col) =
                    __floats2half2_rn(v[0], v[1]);
                *(__half2*)(C + (size_t)(row0 + 8) * N + col) =
                    __floats2half2_rn(v[2], v[3]);
            }
        }
    }
}

// ---------------------------------------------------------------------------
// Fused QKV GEMM. grid.x = 12: weight w = blockIdx.x >> 2,
// bn = (blockIdx.x & 3) * 256. Epilogue: w=0 Q*0.125, w=1 K plain, w=2 V^T.
// ---------------------------------------------------------------------------
__global__ __launch_bounds__(256, 1)
void gemm_qkv(const __half* __restrict__ A,
              const __half* __restrict__ Bq, const __half* __restrict__ Bk,
              const __half* __restrict__ Bv,
              __half* __restrict__ Cq, __half* __restrict__ Ck,
              __half* __restrict__ Cvt)
{
    GEMM_SMEM_PTRS
    GEMM_IDS
    const int K  = DMODEL;
    const int w  = blockIdx.x >> 2;
    const int bn = (blockIdx.x & 3) * 256;
    const int bm = blockIdx.y * 128;

    const __half* Bsel = (w == 0) ? Bq : (w == 1) ? Bk : Bv;
    const __half* Ab = A + (size_t)bm * K;
    const __half* Bb = Bsel + (size_t)bn * K;

    float acc[4][8][4];
#pragma unroll
    for (int i = 0; i < 4; i++)
#pragma unroll
        for (int j = 0; j < 8; j++)
#pragma unroll
            for (int r = 0; r < 4; r++) acc[i][j][r] = 0.f;

    GEMM_MAINLOOP(Ab, Bb, K, acc);

#pragma unroll
    for (int fm = 0; fm < 4; fm++) {
#pragma unroll
        for (int fn = 0; fn < 8; fn++) {
            const int row0 = bm + wm0 + fm * 16 + gid;
            const int col  = bn + wn0 + fn * 8 + tig * 2;
            float* v = acc[fm][fn];
            if (w == 0) {
                *(__half2*)(Cq + (size_t)row0 * DMODEL + col) =
                    __floats2half2_rn(v[0] * 0.125f, v[1] * 0.125f);
                *(__half2*)(Cq + (size_t)(row0 + 8) * DMODEL + col) =
                    __floats2half2_rn(v[2] * 0.125f, v[3] * 0.125f);
            } else if (w == 1) {
                *(__half2*)(Ck + (size_t)row0 * DMODEL + col) =
                    __floats2half2_rn(v[0], v[1]);
                *(__half2*)(Ck + (size_t)(row0 + 8) * DMODEL + col) =
                    __floats2half2_rn(v[2], v[3]);
            } else {
#pragma unroll
                for (int ri = 0; ri < 2; ri++) {
#pragma unroll
                    for (int ci = 0; ci < 2; ci++) {
                        int r = row0 + ri * 8;
                        int c = col + ci;
                        int bb = r >> 11, ss = r & 2047;
                        int hh = c >> 6,  dd = c & 63;
                        Cvt[(((size_t)(bb * 16 + hh)) * 64 + dd) * SEQ + ss] =
                            __float2half(v[ri * 2 + ci]);
                    }
                }
            }
        }
    }
}

// ---------------------------------------------------------------------------
// Flash attention (unchanged from R9): fp16 mma + ldmatrix, Q frags in regs,
// 3-stage KV, single barrier per KV tile, 2 CTAs/SM.
// ---------------------------------------------------------------------------
#define FQS 72
#define KVSTG 3
#define FLASHH_SMEM ((128 * FQS + 2 * KVSTG * 64 * FQS) * 2)   // 73728 B

__global__ __launch_bounds__(256, 2)
void flash_h(const __half* __restrict__ Q, const __half* __restrict__ K,
             const __half* __restrict__ Vt, __half* __restrict__ Oa)
{
    extern __shared__ __half fsh[];
    __half* Qs = fsh;
    const uint32_t qs_u = smem_u32(Qs);
    uint32_t ks_u[KVSTG], vs_u[KVSTG];
#pragma unroll
    for (int s_ = 0; s_ < KVSTG; s_++) {
        ks_u[s_] = smem_u32(Qs + 128 * FQS + s_ * 64 * FQS);
        vs_u[s_] = smem_u32(Qs + 128 * FQS + (KVSTG + s_) * 64 * FQS);
    }

    const int tid = threadIdx.x;
    const int wid = tid >> 5;
    const int lid = tid & 31;
    const int gid = lid >> 2;
    const int tig = lid & 3;
    const int q0  = blockIdx.x * 128;
    const int bh  = blockIdx.y;
    const int b   = bh >> 4;
    const int h   = bh & 15;
    const int m0  = wid * 16;

    const int a_moff = (lid & 7) + ((lid >> 3) & 1) * 8;
    const int a_koff = (lid >> 4) * 8;
    const int b_noff = (lid & 7) + ((lid >> 4) & 1) * 8;
    const int b_koff = ((lid >> 3) & 1) * 8;

    const size_t base = (size_t)b * SEQ * DMODEL + h * DK;
    const __half* Qb = Q + base;
    const __half* Kb = K + base;
    const __half* Vb = Vt + ((size_t)(b * 16 + h)) * 64 * SEQ;
    __half*       Ob = Oa + base;

    // Q tile (group 0)
#pragma unroll
    for (int it = 0; it < 4; it++) {
        int s   = tid + it * 256;
        int row = s >> 3;
        int c8  = (s & 7) << 3;
        CP_ASYNC16(qs_u + (uint32_t)(row * FQS + c8) * 2u,
                   Qb + (size_t)(q0 + row) * DMODEL + c8);
    }
    CP_COMMIT();

    auto load_kv = [&](int kt, int buf) {
        const __half* Kt  = Kb + (size_t)kt * 64 * DMODEL;
        const __half* Vtt = Vb + kt * 64;
#pragma unroll
        for (int it = 0; it < 2; it++) {
            int s   = tid + it * 256;
            int row = s >> 3;
            int c8  = (s & 7) << 3;
            CP_ASYNC16(ks_u[buf] + (uint32_t)(row * FQS + c8) * 2u,
                       Kt + (size_t)row * DMODEL + c8);
            CP_ASYNC16(vs_u[buf] + (uint32_t)(row * FQS + c8) * 2u,
                       Vtt + (size_t)row * SEQ + c8);
        }
        CP_COMMIT();
    };

    load_kv(0, 0);      // group 1
    load_kv(1, 1);      // group 2

    // hoist Q fragments (wait: Q group done; kv0/kv1 may pend)
    CP_WAIT(2);
    __syncthreads();
    uint32_t qf[4][4];
    {
        const uint32_t qB = qs_u + (uint32_t)((m0 + a_moff) * FQS + a_koff) * 2u;
#pragma unroll
        for (int kf = 0; kf < 4; kf++)
            LDSM4(qf[kf], qB + kf * 32);
    }

    float m[2] = { -1e30f, -1e30f };
    float l[2] = { 0.f, 0.f };
    float o[8][4];
#pragma unroll
    for (int d = 0; d < 8; d++)
#pragma unroll
        for (int r = 0; r < 4; r++) o[d][r] = 0.f;

    const int NT = SEQ / 64;

    for (int kt = 0; kt < NT; kt++) {
        const int buf = kt % KVSTG;
        if (kt + 1 < NT) { CP_WAIT(1); } else { CP_WAIT(0); }
        __syncthreads();

        const uint32_t kB = ks_u[buf] + (uint32_t)(b_noff * FQS + b_koff) * 2u;
        const uint32_t vB = vs_u[buf] + (uint32_t)(b_noff * FQS + b_koff) * 2u;

        // ---- S = Q @ K^T ----
        float s[8][4];
#pragma unroll
        for (int nf = 0; nf < 8; nf++)
#pragma unroll
            for (int r = 0; r < 4; r++) s[nf][r] = 0.f;

#pragma unroll
        for (int kf = 0; kf < 4; kf++) {
#pragma unroll
            for (int fn2 = 0; fn2 < 4; fn2++) {
                uint32_t kb[4];
                LDSM4(kb, kB + (uint32_t)(fn2 * 16 * FQS) * 2u + kf * 32);
                MMA_F16(s[2 * fn2],     qf[kf][0], qf[kf][1], qf[kf][2], qf[kf][3],
                        kb[0], kb[1]);
                MMA_F16(s[2 * fn2 + 1], qf[kf][0], qf[kf][1], qf[kf][2], qf[kf][3],
                        kb[2], kb[3]);
            }
        }

        // ---- online softmax ----
        float mx0 = -1e30f, mx1 = -1e30f;
#pragma unroll
        for (int nf = 0; nf < 8; nf++) {
            mx0 = fmaxf(mx0, fmaxf(s[nf][0], s[nf][1]));
            mx1 = fmaxf(mx1, fmaxf(s[nf][2], s[nf][3]));
        }
        mx0 = fmaxf(mx0, __shfl_xor_sync(0xffffffffu, mx0, 1));
        mx0 = fmaxf(mx0, __shfl_xor_sync(0xffffffffu, mx0, 2));
        mx1 = fmaxf(mx1, __shfl_xor_sync(0xffffffffu, mx1, 1));
        mx1 = fmaxf(mx1, __shfl_xor_sync(0xffffffffu, mx1, 2));

        const float mn0 = fmaxf(m[0], mx0);
        const float mn1 = fmaxf(m[1], mx1);
        const float al0 = __expf(m[0] - mn0);
        const float al1 = __expf(m[1] - mn1);

        float sum0 = 0.f, sum1 = 0.f;
#pragma unroll
        for (int nf = 0; nf < 8; nf++) {
            s[nf][0] = __expf(s[nf][0] - mn0);
            s[nf][1] = __expf(s[nf][1] - mn0);
            s[nf][2] = __expf(s[nf][2] - mn1);
            s[nf][3] = __expf(s[nf][3] - mn1);
            sum0 += s[nf][0] + s[nf][1];
            sum1 += s[nf][2] + s[nf][3];
        }
        sum0 += __shfl_xor_sync(0xffffffffu, sum0, 1);
        sum0 += __shfl_xor_sync(0xffffffffu, sum0, 2);
        sum1 += __shfl_xor_sync(0xffffffffu, sum1, 1);
        sum1 += __shfl_xor_sync(0xffffffffu, sum1, 2);

        l[0] = l[0] * al0 + sum0;
        l[1] = l[1] * al1 + sum1;
        m[0] = mn0;
        m[1] = mn1;

#pragma unroll
        for (int d = 0; d < 8; d++) {
            o[d][0] *= al0; o[d][1] *= al0;
            o[d][2] *= al1; o[d][3] *= al1;
        }

        // ---- O += P @ V ----
#pragma unroll
        for (int c = 0; c < 4; c++) {
            uint32_t a0 = pack_h2(s[2*c][0],   s[2*c][1]);
            uint32_t a1 = pack_h2(s[2*c][2],   s[2*c][3]);
            uint32_t a2 = pack_h2(s[2*c+1][0], s[2*c+1][1]);
            uint32_t a3 = pack_h2(s[2*c+1][2], s[2*c+1][3]);
#pragma unroll
            for (int fn2 = 0; fn2 < 4; fn2++) {
                uint32_t vb[4];
                LDSM4(vb, vB + (uint32_t)(fn2 * 16 * FQS) * 2u + c * 32);
                MMA_F16(o[2 * fn2],     a0, a1, a2, a3, vb[0], vb[1]);
                MMA_F16(o[2 * fn2 + 1], a0, a1, a2, a3, vb[2], vb[3]);
            }
        }

        // prefetch kt+2 into stage (kt+2)%3 == (kt-1)%3 (safe: barrier above)
        if (kt + 2 < NT) load_kv(kt + 2, (kt + 2) % KVSTG);
    }

    const float inv0 = 1.f / l[0];
    const float inv1 = 1.f / l[1];
    const int row0 = q0 + m0 + gid;
#pragma unroll
    for (int d = 0; d < 8; d++) {
        const int col = d * 8 + tig * 2;
        *(__half2*)(Ob + (size_t)row0 * DMODEL + col) =
            __floats2half2_rn(o[d][0] * inv0, o[d][1] * inv0);
        *(__half2*)(Ob + (size_t)(row0 + 8) * DMODEL + col) =
            __floats2half2_rn(o[d][2] * inv1, o[d][3] * inv1);
    }
}

// ---------------------------------------------------------------------------
// y = LayerNorm(a + b) * gamma + beta; dual output (fp32 + fp16)
// ---------------------------------------------------------------------------
__global__ __launch_bounds__(256)
void add_ln2(const float* __restrict__ a, const float* __restrict__ b,
             const float* __restrict__ gamma, const float* __restrict__ beta,
             float* __restrict__ y, __half* __restrict__ yh)
{
    const int row = blockIdx.x;
    const int tid = threadIdx.x;
    __shared__ float rs[256], rq[256];

    float4 va = ((const float4*)(a + (size_t)row * DMODEL))[tid];
    float4 vb = ((const float4*)(b + (size_t)row * DMODEL))[tid];
    float s0 = va.x + vb.x, s1 = va.y + vb.y, s2 = va.z + vb.z, s3 = va.w + vb.w;

    rs[tid] = s0 + s1 + s2 + s3;
    rq[tid] = s0 * s0 + s1 * s1 + s2 * s2 + s3 * s3;
    __syncthreads();
#pragma unroll
    for (int off = 128; off > 0; off >>= 1) {
        if (tid < off) { rs[tid] += rs[tid + off]; rq[tid] += rq[tid + off]; }
        __syncthreads();
    }
    const float mu   = rs[0] * (1.f / DMODEL);
    const float var  = rq[0] * (1.f / DMODEL) - mu * mu;
    const float rinv = rsqrtf(var + 1e-5f);

    float4 g  = ((const float4*)gamma)[tid];
    float4 be = ((const float4*)beta)[tid];
    float4 out;
    out.x = (s0 - mu) * rinv * g.x + be.x;
    out.y = (s1 - mu) * rinv * g.y + be.y;
    out.z = (s2 - mu) * rinv * g.z + be.z;
    out.w = (s3 - mu) * rinv * g.w + be.w;
    ((float4*)(y + (size_t)row * DMODEL))[tid] = out;

    __half* hp = yh + (size_t)row * DMODEL + tid * 4;
    *(__half2*)(hp)     = __floats2half2_rn(out.x, out.y);
    *(__half2*)(hp + 2) = __floats2half2_rn(out.z, out.w);
}

// ---------------------------------------------------------------------------
// launch
// ---------------------------------------------------------------------------
extern "C" void kernel_launch(void* const* d_in, const int* in_sizes, int n_in,
                              void* d_out, int out_size)
{
    const float* x  = (const float*)d_in[0];
    const float* Wq = (const float*)d_in[1];
    const float* Wk = (const float*)d_in[2];
    const float* Wv = (const float*)d_in[3];
    const float* Wo = (const float*)d_in[4];
    const float* W1 = (const float*)d_in[5];
    const float* W2 = (const float*)d_in[6];
    const float* g1 = (const float*)d_in[7];
    const float* b1 = (const float*)d_in[8];
    const float* g2 = (const float*)d_in[9];
    const float* b2 = (const float*)d_in[10];
    float* out = (float*)d_out;

    __half *px, *pwq, *pwk, *pwv, *pwo, *pw1, *pw2;
    __half *pq, *pk, *pvt, *pattn, *px1h, *pff;
    float *pproj, *px1;
    cudaGetSymbolAddress((void**)&px,   hx);
    cudaGetSymbolAddress((void**)&pwq,  hWq);
    cudaGetSymbolAddress((void**)&pwk,  hWk);
    cudaGetSymbolAddress((void**)&pwv,  hWv);
    cudaGetSymbolAddress((void**)&pwo,  hWo);
    cudaGetSymbolAddress((void**)&pw1,  hW1);
    cudaGetSymbolAddress((void**)&pw2,  hW2);
    cudaGetSymbolAddress((void**)&pq,   hq);
    cudaGetSymbolAddress((void**)&pk,   hk);
    cudaGetSymbolAddress((void**)&pvt,  hvt);
    cudaGetSymbolAddress((void**)&pattn,hattn);
    cudaGetSymbolAddress((void**)&px1h, hx1);
    cudaGetSymbolAddress((void**)&pff,  hff);
    cudaGetSymbolAddress((void**)&pproj,g_proj);
    cudaGetSymbolAddress((void**)&px1,  g_x1);

    cudaFuncSetAttribute(gemm256<0>, cudaFuncAttributeMaxDynamicSharedMemorySize, GEMM_SMEM);
    cudaFuncSetAttribute(gemm256<3>, cudaFuncAttributeMaxDynamicSharedMemorySize, GEMM_SMEM);
    cudaFuncSetAttribute(gemm256<4>, cudaFuncAttributeMaxDynamicSharedMemorySize, GEMM_SMEM);
    cudaFuncSetAttribute(gemm_qkv,   cudaFuncAttributeMaxDynamicSharedMemorySize, GEMM_SMEM);
    cudaFuncSetAttribute(flash_h,    cudaFuncAttributeMaxDynamicSharedMemorySize, FLASHH_SMEM);

    dim3 blk(256);

    // fp32 -> fp16, single launch
    f2h_all<<<dim3(TOKENS * DMODEL / 1024, 7), blk>>>(
        x, px, Wq, pwq, Wk, pwk, Wv, pwv, Wo, pwo, W1, pw1, W2, pw2);

    // fused QKV projections (grid.x = 3 weights * 4 n-tiles)
    gemm_qkv<<<dim3(12, TOKENS / 128), blk, GEMM_SMEM>>>(
        px, pwq, pwk, pwv, pq, pk, pvt);

    // attention
    dim3 gattn(SEQ / 128, 2 * NHEADS);
    flash_h<<<gattn, blk, FLASHH_SMEM>>>(pq, pk, pvt, pattn);

    // output projection + residual + LN1
    gemm256<4><<<dim3(DMODEL / 256, TOKENS / 128), blk, GEMM_SMEM>>>(
        pattn, pwo, pproj, TOKENS, DMODEL, DMODEL);
    add_ln2<<<TOKENS, 256>>>(x, pproj, g1, b1, px1, px1h);

    // FF1 (+GELU), FF2, residual + LN2
    gemm256<3><<<dim3(DFF / 256, TOKENS / 128), blk, GEMM_SMEM>>>(
        px1h, pw1, pff, TOKENS, DFF, DMODEL);
    gemm256<4><<<dim3(DMODEL / 256, TOKENS / 128), blk, GEMM_SMEM>>>(
        pff, pw2, pproj, TOKENS, DMODEL, DFF);
    add_ln2<<<TOKENS, 256>>>(px1, pproj, g2, b2, out, px1h);
}

// round 12
// speedup vs baseline: 1.0880x; 1.0880x over previous
#include <cuda_runtime.h>
#include <cuda_fp16.h>
#include <math.h>
#include <cstdint>

// ---------------------------------------------------------------------------
// Problem constants
// ---------------------------------------------------------------------------
#define TOKENS 4096        // B*S = 2*2048
#define DMODEL 1024
#define DFF    4096
#define NHEADS 16
#define DK     64
#define SEQ    2048

// Q pre-scale: 1/sqrt(64) * log2(e) -> softmax computed with ex2
#define QSCALE 0.18033688011112042f

// ---------------------------------------------------------------------------
// Scratch (device globals)
// ---------------------------------------------------------------------------
__device__ __half hx   [TOKENS * DMODEL];
__device__ __half hWq  [DMODEL * DMODEL];
__device__ __half hWk  [DMODEL * DMODEL];
__device__ __half hWv  [DMODEL * DMODEL];
__device__ __half hWo  [DMODEL * DMODEL];
__device__ __half hW1  [DFF * DMODEL];
__device__ __half hW2  [DMODEL * DFF];
__device__ __half hq   [TOKENS * DMODEL];   // pre-scaled by QSCALE
__device__ __half hk   [TOKENS * DMODEL];
__device__ __half hvt  [TOKENS * DMODEL];   // V transposed: [b][h][d][s]
__device__ __half hattn[TOKENS * DMODEL];
__device__ __half hx1  [TOKENS * DMODEL];
__device__ __half hff  [TOKENS * DFF];
__device__ float  g_proj[TOKENS * DMODEL];
__device__ float  g_x1 [TOKENS * DMODEL];

// ---------------------------------------------------------------------------
// Helpers
// ---------------------------------------------------------------------------
__device__ __forceinline__ uint32_t smem_u32(const void* p) {
    uint32_t a;
    asm("{ .reg .u64 t; cvta.to.shared.u64 t, %1; cvt.u32.u64 %0, t; }"
        : "=r"(a) : "l"(p));
    return a;
}

__device__ __forceinline__ float ex2f(float x) {
    float r;
    asm("ex2.approx.f32 %0, %1;" : "=f"(r) : "f"(x));
    return r;
}

#define CP_ASYNC16(dst_u32, src_ptr) \
    asm volatile("cp.async.cg.shared.global [%0], [%1], 16;" \
        :: "r"(dst_u32), "l"(src_ptr))
#define CP_COMMIT() asm volatile("cp.async.commit_group;")
#define CP_WAIT(n)  asm volatile("cp.async.wait_group %0;" :: "n"(n))

#define MMA_F16(c, a0, a1, a2, a3, b0, b1) \
    asm volatile("mma.sync.aligned.m16n8k16.row.col.f32.f16.f16.f32 " \
        "{%0,%1,%2,%3}, {%4,%5,%6,%7}, {%8,%9}, {%0,%1,%2,%3};" \
        : "+f"((c)[0]), "+f"((c)[1]), "+f"((c)[2]), "+f"((c)[3]) \
        : "r"(a0), "r"(a1), "r"(a2), "r"(a3), "r"(b0), "r"(b1))

#define LDSM4(r, addr) \
    asm volatile("ldmatrix.sync.aligned.m8n8.x4.shared.b16 {%0,%1,%2,%3}, [%4];" \
        : "=r"((r)[0]), "=r"((r)[1]), "=r"((r)[2]), "=r"((r)[3]) : "r"(addr))

__device__ __forceinline__ uint32_t pack_h2(float lo, float hi) {
    __half2 h = __floats2half2_rn(lo, hi);
    return *reinterpret_cast<uint32_t*>(&h);
}

// ---------------------------------------------------------------------------
// fp32 -> fp16 conversion, all tensors in one launch (grid.y selects tensor)
// ---------------------------------------------------------------------------
__global__ __launch_bounds__(256)
void f2h_all(const float* x,  __half* dx,
             const float* w0, __half* d0, const float* w1, __half* d1,
             const float* w2, __half* d2, const float* w3, __half* d3,
             const float* w4, __half* d4, const float* w5, __half* d5)
{
    const float* src; __half* dst; int n;
    switch (blockIdx.y) {
        case 0: src = x;  dst = dx; n = TOKENS * DMODEL; break;
        case 1: src = w0; dst = d0; n = DMODEL * DMODEL; break;
        case 2: src = w1; dst = d1; n = DMODEL * DMODEL; break;
        case 3: src = w2; dst = d2; n = DMODEL * DMODEL; break;
        case 4: src = w3; dst = d3; n = DMODEL * DMODEL; break;
        case 5: src = w4; dst = d4; n = DFF * DMODEL;    break;
        default:src = w5; dst = d5; n = DMODEL * DFF;    break;
    }
    int i = (blockIdx.x * 256 + threadIdx.x) * 4;
    if (i < n) {
        float4 v = *(const float4*)(src + i);
        *(__half2*)(dst + i)     = __floats2half2_rn(v.x, v.y);
        *(__half2*)(dst + i + 2) = __floats2half2_rn(v.z, v.w);
    }
}

// ---------------------------------------------------------------------------
// 128(M) x 128(N) x BK=64 fp16 GEMM, 3-stage cp.async, 2 CTAs/SM,
// single-barrier multistage mainloop (R9 proven config).
// ---------------------------------------------------------------------------
#define HSTR   72
#define OPTILE (128 * HSTR)
#define NSTAGE 3
#define GEMM_SMEM (2 * NSTAGE * OPTILE * 2)      // 110592 B

#define GEMM_IDS \
    const int tid = threadIdx.x; \
    const int wid = tid >> 5; \
    const int lid = tid & 31; \
    const int gid = lid >> 2; \
    const int tig = lid & 3; \
    const int wm0 = (wid & 1) * 64; \
    const int wn0 = (wid >> 1) * 32; \
    const int ldRow = tid >> 3; \
    const int ldC8  = (tid & 7) << 3; \
    const int a_moff = (lid & 7) + ((lid >> 3) & 1) * 8; \
    const int a_koff = (lid >> 4) * 8; \
    const int b_noff = (lid & 7) + ((lid >> 4) & 1) * 8; \
    const int b_koff = ((lid >> 3) & 1) * 8;

#define GEMM_SMEM_PTRS \
    extern __shared__ __half hsm[]; \
    uint32_t sA_u[NSTAGE], sB_u[NSTAGE]; \
    _Pragma("unroll") \
    for (int s_ = 0; s_ < NSTAGE; s_++) { \
        sA_u[s_] = smem_u32(hsm + s_ * OPTILE); \
        sB_u[s_] = smem_u32(hsm + (NSTAGE + s_) * OPTILE); \
    }

#define GEMM_LOAD_TILE(kt, buf, Ab, Bb, K) do { \
    const __half* Ak_ = (Ab) + (size_t)(kt) * 64; \
    const __half* Bk_ = (Bb) + (size_t)(kt) * 64; \
    _Pragma("unroll") \
    for (int it = 0; it < 4; it++) { \
        int row = ldRow + it * 32; \
        uint32_t so_ = (uint32_t)(row * HSTR + ldC8) * 2u; \
        CP_ASYNC16(sA_u[buf] + so_, Ak_ + (size_t)row * (K) + ldC8); \
        CP_ASYNC16(sB_u[buf] + so_, Bk_ + (size_t)row * (K) + ldC8); \
    } \
    CP_COMMIT(); \
} while (0)

#define GEMM_COMPUTE_TILE(buf, acc) do { \
    const uint32_t aB_ = sA_u[buf] + (uint32_t)((wm0 + a_moff) * HSTR + a_koff) * 2u; \
    const uint32_t bB_ = sB_u[buf] + (uint32_t)((wn0 + b_noff) * HSTR + b_koff) * 2u; \
    _Pragma("unroll") \
    for (int ks = 0; ks < 4; ks++) { \
        uint32_t a[4][4], b[2][4]; \
        _Pragma("unroll") \
        for (int fm = 0; fm < 4; fm++) \
            LDSM4(a[fm], aB_ + (uint32_t)(fm * 16 * HSTR) * 2u + ks * 32); \
        _Pragma("unroll") \
        for (int fn2 = 0; fn2 < 2; fn2++) \
            LDSM4(b[fn2], bB_ + (uint32_t)(fn2 * 16 * HSTR) * 2u + ks * 32); \
        _Pragma("unroll") \
        for (int fm = 0; fm < 4; fm++) \
            _Pragma("unroll") \
            for (int fn = 0; fn < 4; fn++) \
                MMA_F16(acc[fm][fn], \
                        a[fm][0], a[fm][1], a[fm][2], a[fm][3], \
                        b[fn >> 1][(fn & 1) * 2], b[fn >> 1][(fn & 1) * 2 + 1]); \
    } \
} while (0)

// Single-barrier multistage: wait(kt) -> barrier -> compute(kt) -> load(kt+2).
#define GEMM_MAINLOOP(Ab, Bb, K, acc) do { \
    const int KT_ = (K) >> 6; \
    GEMM_LOAD_TILE(0, 0, Ab, Bb, K); \
    GEMM_LOAD_TILE(1, 1, Ab, Bb, K); \
    for (int kt = 0; kt < KT_; kt++) { \
        if (kt + 1 < KT_) { CP_WAIT(1); } else { CP_WAIT(0); } \
        __syncthreads(); \
        GEMM_COMPUTE_TILE(kt % NSTAGE, acc); \
        if (kt + 2 < KT_) GEMM_LOAD_TILE(kt + 2, (kt + 2) % NSTAGE, Ab, Bb, K); \
    } \
} while (0)

// ---------------------------------------------------------------------------
// General GEMM:  C[M,N] = A[M,K] @ B[N,K]^T
// EPI: 0 = fp16, 3 = exact GELU -> fp16, 4 = fp32
// ---------------------------------------------------------------------------
template <int EPI>
__global__ __launch_bounds__(256, 2)
void gemm128(const __half* __restrict__ A, const __half* __restrict__ B,
             void* __restrict__ Cv, int M, int N, int K)
{
    GEMM_SMEM_PTRS
    GEMM_IDS
    const int bm = blockIdx.y * 128;
    const int bn = blockIdx.x * 128;

    const __half* Ab = A + (size_t)bm * K;
    const __half* Bb = B + (size_t)bn * K;

    float acc[4][4][4];
#pragma unroll
    for (int i = 0; i < 4; i++)
#pragma unroll
        for (int j = 0; j < 4; j++)
#pragma unroll
            for (int r = 0; r < 4; r++) acc[i][j][r] = 0.f;

    GEMM_MAINLOOP(Ab, Bb, K, acc);

#pragma unroll
    for (int fm = 0; fm < 4; fm++) {
#pragma unroll
        for (int fn = 0; fn < 4; fn++) {
            float v[4];
#pragma unroll
            for (int r = 0; r < 4; r++) {
                float t = acc[fm][fn][r];
                if (EPI == 3) t = 0.5f * t * (1.f + erff(t * 0.70710678118654752f));
                v[r] = t;
            }
            const int row0 = bm + wm0 + fm * 16 + gid;
            const int col  = bn + wn0 + fn * 8 + tig * 2;
            if (EPI == 4) {
                float* C = (float*)Cv;
                *(float2*)(C + (size_t)row0 * N + col)       = make_float2(v[0], v[1]);
                *(float2*)(C + (size_t)(row0 + 8) * N + col) = make_float2(v[2], v[3]);
            } else {
                __half* C = (__half*)Cv;
                *(__half2*)(C + (size_t)row0 * N + col) =
                    __floats2half2_rn(v[0], v[1]);
                *(__half2*)(C + (size_t)(row0 + 8) * N + col) =
                    __floats2half2_rn(v[2], v[3]);
            }
        }
    }
}

// ---------------------------------------------------------------------------
// Fused QKV GEMM. grid.x = 24: weight w = blockIdx.x >> 3,
// bn = (blockIdx.x & 7) * 128. Epilogue: w=0 Q*QSCALE, w=1 K plain, w=2 V^T.
// ---------------------------------------------------------------------------
__global__ __launch_bounds__(256, 2)
void gemm_qkv(const __half* __restrict__ A,
              const __half* __restrict__ Bq, const __half* __restrict__ Bk,
              const __half* __restrict__ Bv,
              __half* __restrict__ Cq, __half* __restrict__ Ck,
              __half* __restrict__ Cvt)
{
    GEMM_SMEM_PTRS
    GEMM_IDS
    const int K  = DMODEL;
    const int w  = blockIdx.x >> 3;
    const int bn = (blockIdx.x & 7) * 128;
    const int bm = blockIdx.y * 128;

    const __half* Bsel = (w == 0) ? Bq : (w == 1) ? Bk : Bv;
    const __half* Ab = A + (size_t)bm * K;
    const __half* Bb = Bsel + (size_t)bn * K;

    float acc[4][4][4];
#pragma unroll
    for (int i = 0; i < 4; i++)
#pragma unroll
        for (int j = 0; j < 4; j++)
#pragma unroll
            for (int r = 0; r < 4; r++) acc[i][j][r] = 0.f;

    GEMM_MAINLOOP(Ab, Bb, K, acc);

#pragma unroll
    for (int fm = 0; fm < 4; fm++) {
#pragma unroll
        for (int fn = 0; fn < 4; fn++) {
            const int row0 = bm + wm0 + fm * 16 + gid;
            const int col  = bn + wn0 + fn * 8 + tig * 2;
            float* v = acc[fm][fn];
            if (w == 0) {
                *(__half2*)(Cq + (size_t)row0 * DMODEL + col) =
                    __floats2half2_rn(v[0] * QSCALE, v[1] * QSCALE);
                *(__half2*)(Cq + (size_t)(row0 + 8) * DMODEL + col) =
                    __floats2half2_rn(v[2] * QSCALE, v[3] * QSCALE);
            } else if (w == 1) {
                *(__half2*)(Ck + (size_t)row0 * DMODEL + col) =
                    __floats2half2_rn(v[0], v[1]);
                *(__half2*)(Ck + (size_t)(row0 + 8) * DMODEL + col) =
                    __floats2half2_rn(v[2], v[3]);
            } else {
#pragma unroll
                for (int ri = 0; ri < 2; ri++) {
#pragma unroll
                    for (int ci = 0; ci < 2; ci++) {
                        int r = row0 + ri * 8;
                        int c = col + ci;
                        int bb = r >> 11, ss = r & 2047;
                        int hh = c >> 6,  dd = c & 63;
                        Cvt[(((size_t)(bb * 16 + hh)) * 64 + dd) * SEQ + ss] =
                            __float2half(v[ri * 2 + ci]);
                    }
                }
            }
        }
    }
}

// ---------------------------------------------------------------------------
// Flash attention: fp16 mma + ldmatrix, Q frags in regs, 3-stage KV,
// single barrier per KV tile, 2 CTAs/SM. Softmax in log2 domain (Q carries
// the log2(e) factor), p/alpha via raw ex2.approx.
// ---------------------------------------------------------------------------
#define FQS 72
#define KVSTG 3
#define FLASHH_SMEM ((128 * FQS + 2 * KVSTG * 64 * FQS) * 2)   // 73728 B

__global__ __launch_bounds__(256, 2)
void flash_h(const __half* __restrict__ Q, const __half* __restrict__ K,
             const __half* __restrict__ Vt, __half* __restrict__ Oa)
{
    extern __shared__ __half fsh[];
    __half* Qs = fsh;
    const uint32_t qs_u = smem_u32(Qs);
    uint32_t ks_u[KVSTG], vs_u[KVSTG];
#pragma unroll
    for (int s_ = 0; s_ < KVSTG; s_++) {
        ks_u[s_] = smem_u32(Qs + 128 * FQS + s_ * 64 * FQS);
        vs_u[s_] = smem_u32(Qs + 128 * FQS + (KVSTG + s_) * 64 * FQS);
    }

    const int tid = threadIdx.x;
    const int wid = tid >> 5;
    const int lid = tid & 31;
    const int gid = lid >> 2;
    const int tig = lid & 3;
    const int q0  = blockIdx.x * 128;
    const int bh  = blockIdx.y;
    const int b   = bh >> 4;
    const int h   = bh & 15;
    const int m0  = wid * 16;

    const int a_moff = (lid & 7) + ((lid >> 3) & 1) * 8;
    const int a_koff = (lid >> 4) * 8;
    const int b_noff = (lid & 7) + ((lid >> 4) & 1) * 8;
    const int b_koff = ((lid >> 3) & 1) * 8;

    const size_t base = (size_t)b * SEQ * DMODEL + h * DK;
    const __half* Qb = Q + base;
    const __half* Kb = K + base;
    const __half* Vb = Vt + ((size_t)(b * 16 + h)) * 64 * SEQ;
    __half*       Ob = Oa + base;

    // Q tile (group 0)
#pragma unroll
    for (int it = 0; it < 4; it++) {
        int s   = tid + it * 256;
        int row = s >> 3;
        int c8  = (s & 7) << 3;
        CP_ASYNC16(qs_u + (uint32_t)(row * FQS + c8) * 2u,
                   Qb + (size_t)(q0 + row) * DMODEL + c8);
    }
    CP_COMMIT();

    auto load_kv = [&](int kt, int buf) {
        const __half* Kt  = Kb + (size_t)kt * 64 * DMODEL;
        const __half* Vtt = Vb + kt * 64;
#pragma unroll
        for (int it = 0; it < 2; it++) {
            int s   = tid + it * 256;
            int row = s >> 3;
            int c8  = (s & 7) << 3;
            CP_ASYNC16(ks_u[buf] + (uint32_t)(row * FQS + c8) * 2u,
                       Kt + (size_t)row * DMODEL + c8);
            CP_ASYNC16(vs_u[buf] + (uint32_t)(row * FQS + c8) * 2u,
                       Vtt + (size_t)row * SEQ + c8);
        }
        CP_COMMIT();
    };

    load_kv(0, 0);      // group 1
    load_kv(1, 1);      // group 2

    // hoist Q fragments (wait: Q group done; kv0/kv1 may pend)
    CP_WAIT(2);
    __syncthreads();
    uint32_t qf[4][4];
    {
        const uint32_t qB = qs_u + (uint32_t)((m0 + a_moff) * FQS + a_koff) * 2u;
#pragma unroll
        for (int kf = 0; kf < 4; kf++)
            LDSM4(qf[kf], qB + kf * 32);
    }

    float m[2] = { -1e30f, -1e30f };
    float l[2] = { 0.f, 0.f };
    float o[8][4];
#pragma unroll
    for (int d = 0; d < 8; d++)
#pragma unroll
        for (int r = 0; r < 4; r++) o[d][r] = 0.f;

    const int NT = SEQ / 64;

    for (int kt = 0; kt < NT; kt++) {
        const int buf = kt % KVSTG;
        if (kt + 1 < NT) { CP_WAIT(1); } else { CP_WAIT(0); }
        __syncthreads();

        const uint32_t kB = ks_u[buf] + (uint32_t)(b_noff * FQS + b_koff) * 2u;
        const uint32_t vB = vs_u[buf] + (uint32_t)(b_noff * FQS + b_koff) * 2u;

        // ---- S = Q @ K^T (log2-domain scores) ----
        float s[8][4];
#pragma unroll
        for (int nf = 0; nf < 8; nf++)
#pragma unroll
            for (int r = 0; r < 4; r++) s[nf][r] = 0.f;

#pragma unroll
        for (int kf = 0; kf < 4; kf++) {
#pragma unroll
            for (int fn2 = 0; fn2 < 4; fn2++) {
                uint32_t kb[4];
                LDSM4(kb, kB + (uint32_t)(fn2 * 16 * FQS) * 2u + kf * 32);
                MMA_F16(s[2 * fn2],     qf[kf][0], qf[kf][1], qf[kf][2], qf[kf][3],
                        kb[0], kb[1]);
                MMA_F16(s[2 * fn2 + 1], qf[kf][0], qf[kf][1], qf[kf][2], qf[kf][3],
                        kb[2], kb[3]);
            }
        }

        // ---- online softmax (base-2) ----
        float mx0 = -1e30f, mx1 = -1e30f;
#pragma unroll
        for (int nf = 0; nf < 8; nf++) {
            mx0 = fmaxf(mx0, fmaxf(s[nf][0], s[nf][1]));
            mx1 = fmaxf(mx1, fmaxf(s[nf][2], s[nf][3]));
        }
        mx0 = fmaxf(mx0, __shfl_xor_sync(0xffffffffu, mx0, 1));
        mx0 = fmaxf(mx0, __shfl_xor_sync(0xffffffffu, mx0, 2));
        mx1 = fmaxf(mx1, __shfl_xor_sync(0xffffffffu, mx1, 1));
        mx1 = fmaxf(mx1, __shfl_xor_sync(0xffffffffu, mx1, 2));

        const float mn0 = fmaxf(m[0], mx0);
        const float mn1 = fmaxf(m[1], mx1);
        const float al0 = ex2f(m[0] - mn0);
        const float al1 = ex2f(m[1] - mn1);

        float sum0 = 0.f, sum1 = 0.f;
#pragma unroll
        for (int nf = 0; nf < 8; nf++) {
            s[nf][0] = ex2f(s[nf][0] - mn0);
            s[nf][1] = ex2f(s[nf][1] - mn0);
            s[nf][2] = ex2f(s[nf][2] - mn1);
            s[nf][3] = ex2f(s[nf][3] - mn1);
            sum0 += s[nf][0] + s[nf][1];
            sum1 += s[nf][2] + s[nf][3];
        }
        sum0 += __shfl_xor_sync(0xffffffffu, sum0, 1);
        sum0 += __shfl_xor_sync(0xffffffffu, sum0, 2);
        sum1 += __shfl_xor_sync(0xffffffffu, sum1, 1);
        sum1 += __shfl_xor_sync(0xffffffffu, sum1, 2);

        l[0] = l[0] * al0 + sum0;
        l[1] = l[1] * al1 + sum1;
        m[0] = mn0;
        m[1] = mn1;

#pragma unroll
        for (int d = 0; d < 8; d++) {
            o[d][0] *= al0; o[d][1] *= al0;
            o[d][2] *= al1; o[d][3] *= al1;
        }

        // ---- O += P @ V ----
#pragma unroll
        for (int c = 0; c < 4; c++) {
            uint32_t a0 = pack_h2(s[2*c][0],   s[2*c][1]);
            uint32_t a1 = pack_h2(s[2*c][2],   s[2*c][3]);
            uint32_t a2 = pack_h2(s[2*c+1][0], s[2*c+1][1]);
            uint32_t a3 = pack_h2(s[2*c+1][2], s[2*c+1][3]);
#pragma unroll
            for (int fn2 = 0; fn2 < 4; fn2++) {
                uint32_t vb[4];
                LDSM4(vb, vB + (uint32_t)(fn2 * 16 * FQS) * 2u + c * 32);
                MMA_F16(o[2 * fn2],     a0, a1, a2, a3, vb[0], vb[1]);
                MMA_F16(o[2 * fn2 + 1], a0, a1, a2, a3, vb[2], vb[3]);
            }
        }

        // prefetch kt+2 into stage (kt+2)%3 == (kt-1)%3 (safe: barrier above)
        if (kt + 2 < NT) load_kv(kt + 2, (kt + 2) % KVSTG);
    }

    const float inv0 = 1.f / l[0];
    const float inv1 = 1.f / l[1];
    const int row0 = q0 + m0 + gid;
#pragma unroll
    for (int d = 0; d < 8; d++) {
        const int col = d * 8 + tig * 2;
        *(__half2*)(Ob + (size_t)row0 * DMODEL + col) =
            __floats2half2_rn(o[d][0] * inv0, o[d][1] * inv0);
        *(__half2*)(Ob + (size_t)(row0 + 8) * DMODEL + col) =
            __floats2half2_rn(o[d][2] * inv1, o[d][3] * inv1);
    }
}

// ---------------------------------------------------------------------------
// y = LayerNorm(a + b) * gamma + beta; dual output (fp32 + fp16)
// ---------------------------------------------------------------------------
__global__ __launch_bounds__(256)
void add_ln2(const float* __restrict__ a, const float* __restrict__ b,
             const float* __restrict__ gamma, const float* __restrict__ beta,
             float* __restrict__ y, __half* __restrict__ yh)
{
    const int row = blockIdx.x;
    const int tid = threadIdx.x;
    __shared__ float rs[256], rq[256];

    float4 va = ((const float4*)(a + (size_t)row * DMODEL))[tid];
    float4 vb = ((const float4*)(b + (size_t)row * DMODEL))[tid];
    float s0 = va.x + vb.x, s1 = va.y + vb.y, s2 = va.z + vb.z, s3 = va.w + vb.w;

    rs[tid] = s0 + s1 + s2 + s3;
    rq[tid] = s0 * s0 + s1 * s1 + s2 * s2 + s3 * s3;
    __syncthreads();
#pragma unroll
    for (int off = 128; off > 0; off >>= 1) {
        if (tid < off) { rs[tid] += rs[tid + off]; rq[tid] += rq[tid + off]; }
        __syncthreads();
    }
    const float mu   = rs[0] * (1.f / DMODEL);
    const float var  = rq[0] * (1.f / DMODEL) - mu * mu;
    const float rinv = rsqrtf(var + 1e-5f);

    float4 g  = ((const float4*)gamma)[tid];
    float4 be = ((const float4*)beta)[tid];
    float4 out;
    out.x = (s0 - mu) * rinv * g.x + be.x;
    out.y = (s1 - mu) * rinv * g.y + be.y;
    out.z = (s2 - mu) * rinv * g.z + be.z;
    out.w = (s3 - mu) * rinv * g.w + be.w;
    ((float4*)(y + (size_t)row * DMODEL))[tid] = out;

    __half* hp = yh + (size_t)row * DMODEL + tid * 4;
    *(__half2*)(hp)     = __floats2half2_rn(out.x, out.y);
    *(__half2*)(hp + 2) = __floats2half2_rn(out.z, out.w);
}

// ---------------------------------------------------------------------------
// launch
// ---------------------------------------------------------------------------
extern "C" void kernel_launch(void* const* d_in, const int* in_sizes, int n_in,
                              void* d_out, int out_size)
{
    const float* x  = (const float*)d_in[0];
    const float* Wq = (const float*)d_in[1];
    const float* Wk = (const float*)d_in[2];
    const float* Wv = (const float*)d_in[3];
    const float* Wo = (const float*)d_in[4];
    const float* W1 = (const float*)d_in[5];
    const float* W2 = (const float*)d_in[6];
    const float* g1 = (const float*)d_in[7];
    const float* b1 = (const float*)d_in[8];
    const float* g2 = (const float*)d_in[9];
    const float* b2 = (const float*)d_in[10];
    float* out = (float*)d_out;

    __half *px, *pwq, *pwk, *pwv, *pwo, *pw1, *pw2;
    __half *pq, *pk, *pvt, *pattn, *px1h, *pff;
    float *pproj, *px1;
    cudaGetSymbolAddress((void**)&px,   hx);
    cudaGetSymbolAddress((void**)&pwq,  hWq);
    cudaGetSymbolAddress((void**)&pwk,  hWk);
    cudaGetSymbolAddress((void**)&pwv,  hWv);
    cudaGetSymbolAddress((void**)&pwo,  hWo);
    cudaGetSymbolAddress((void**)&pw1,  hW1);
    cudaGetSymbolAddress((void**)&pw2,  hW2);
    cudaGetSymbolAddress((void**)&pq,   hq);
    cudaGetSymbolAddress((void**)&pk,   hk);
    cudaGetSymbolAddress((void**)&pvt,  hvt);
    cudaGetSymbolAddress((void**)&pattn,hattn);
    cudaGetSymbolAddress((void**)&px1h, hx1);
    cudaGetSymbolAddress((void**)&pff,  hff);
    cudaGetSymbolAddress((void**)&pproj,g_proj);
    cudaGetSymbolAddress((void**)&px1,  g_x1);

    cudaFuncSetAttribute(gemm128<0>, cudaFuncAttributeMaxDynamicSharedMemorySize, GEMM_SMEM);
    cudaFuncSetAttribute(gemm128<3>, cudaFuncAttributeMaxDynamicSharedMemorySize, GEMM_SMEM);
    cudaFuncSetAttribute(gemm128<4>, cudaFuncAttributeMaxDynamicSharedMemorySize, GEMM_SMEM);
    cudaFuncSetAttribute(gemm_qkv,   cudaFuncAttributeMaxDynamicSharedMemorySize, GEMM_SMEM);
    cudaFuncSetAttribute(flash_h,    cudaFuncAttributeMaxDynamicSharedMemorySize, FLASHH_SMEM);

    dim3 blk(256);

    // fp32 -> fp16, single launch
    f2h_all<<<dim3(TOKENS * DMODEL / 1024, 7), blk>>>(
        x, px, Wq, pwq, Wk, pwk, Wv, pwv, Wo, pwo, W1, pw1, W2, pw2);

    // fused QKV projections (grid.x = 3 weights * 8 n-tiles)
    gemm_qkv<<<dim3(24, TOKENS / 128), blk, GEMM_SMEM>>>(
        px, pwq, pwk, pwv, pq, pk, pvt);

    // attention
    dim3 gattn(SEQ / 128, 2 * NHEADS);
    flash_h<<<gattn, blk, FLASHH_SMEM>>>(pq, pk, pvt, pattn);

    // output projection + residual + LN1
    gemm128<4><<<dim3(DMODEL / 128, TOKENS / 128), blk, GEMM_SMEM>>>(
        pattn, pwo, pproj, TOKENS, DMODEL, DMODEL);
    add_ln2<<<TOKENS, 256>>>(x, pproj, g1, b1, px1, px1h);

    // FF1 (+GELU), FF2, residual + LN2
    gemm128<3><<<dim3(DFF / 128, TOKENS / 128), blk, GEMM_SMEM>>>(
        px1h, pw1, pff, TOKENS, DFF, DMODEL);
    gemm128<4><<<dim3(DMODEL / 128, TOKENS / 128), blk, GEMM_SMEM>>>(
        pff, pw2, pproj, TOKENS, DMODEL, DFF);
    add_ln2<<<TOKENS, 256>>>(px1, pproj, g2, b2, out, px1h);
}

// round 13
// speedup vs baseline: 1.0970x; 1.0082x over previous
#include <cuda_runtime.h>
#include <cuda_fp16.h>
#include <math.h>
#include <cstdint>

// ---------------------------------------------------------------------------
// Problem constants
// ---------------------------------------------------------------------------
#define TOKENS 4096        // B*S = 2*2048
#define DMODEL 1024
#define DFF    4096
#define NHEADS 16
#define DK     64
#define SEQ    2048

// Q pre-scale: 1/sqrt(64) * log2(e) -> softmax computed with ex2
#define QSCALE 0.18033688011112042f

// ---------------------------------------------------------------------------
// Scratch (device globals)
// ---------------------------------------------------------------------------
__device__ __half hx   [TOKENS * DMODEL];
__device__ __half hWq  [DMODEL * DMODEL];
__device__ __half hWk  [DMODEL * DMODEL];
__device__ __half hWv  [DMODEL * DMODEL];
__device__ __half hWo  [DMODEL * DMODEL];
__device__ __half hW1  [DFF * DMODEL];
__device__ __half hW2  [DMODEL * DFF];
__device__ __half hq   [TOKENS * DMODEL];   // pre-scaled by QSCALE
__device__ __half hk   [TOKENS * DMODEL];
__device__ __half hvt  [TOKENS * DMODEL];   // V transposed: [b][h][d][s]
__device__ __half hattn[TOKENS * DMODEL];
__device__ __half hx1  [TOKENS * DMODEL];
__device__ __half hff  [TOKENS * DFF];
__device__ float  g_proj[TOKENS * DMODEL];
__device__ float  g_x1 [TOKENS * DMODEL];

// ---------------------------------------------------------------------------
// Helpers
// ---------------------------------------------------------------------------
__device__ __forceinline__ uint32_t smem_u32(const void* p) {
    uint32_t a;
    asm("{ .reg .u64 t; cvta.to.shared.u64 t, %1; cvt.u32.u64 %0, t; }"
        : "=r"(a) : "l"(p));
    return a;
}

__device__ __forceinline__ float ex2f(float x) {
    float r;
    asm("ex2.approx.f32 %0, %1;" : "=f"(r) : "f"(x));
    return r;
}

#define CP_ASYNC16(dst_u32, src_ptr) \
    asm volatile("cp.async.cg.shared.global [%0], [%1], 16;" \
        :: "r"(dst_u32), "l"(src_ptr))
#define CP_COMMIT() asm volatile("cp.async.commit_group;")
#define CP_WAIT(n)  asm volatile("cp.async.wait_group %0;" :: "n"(n))

#define MMA_F16(c, a0, a1, a2, a3, b0, b1) \
    asm volatile("mma.sync.aligned.m16n8k16.row.col.f32.f16.f16.f32 " \
        "{%0,%1,%2,%3}, {%4,%5,%6,%7}, {%8,%9}, {%0,%1,%2,%3};" \
        : "+f"((c)[0]), "+f"((c)[1]), "+f"((c)[2]), "+f"((c)[3]) \
        : "r"(a0), "r"(a1), "r"(a2), "r"(a3), "r"(b0), "r"(b1))

#define LDSM4(r, addr) \
    asm volatile("ldmatrix.sync.aligned.m8n8.x4.shared.b16 {%0,%1,%2,%3}, [%4];" \
        : "=r"((r)[0]), "=r"((r)[1]), "=r"((r)[2]), "=r"((r)[3]) : "r"(addr))

__device__ __forceinline__ uint32_t pack_h2(float lo, float hi) {
    __half2 h = __floats2half2_rn(lo, hi);
    return *reinterpret_cast<uint32_t*>(&h);
}

// ---------------------------------------------------------------------------
// fp32 -> fp16 conversion, all tensors in one launch (grid.y selects tensor)
// ---------------------------------------------------------------------------
__global__ __launch_bounds__(256)
void f2h_all(const float* x,  __half* dx,
             const float* w0, __half* d0, const float* w1, __half* d1,
             const float* w2, __half* d2, const float* w3, __half* d3,
             const float* w4, __half* d4, const float* w5, __half* d5)
{
    const float* src; __half* dst; int n;
    switch (blockIdx.y) {
        case 0: src = x;  dst = dx; n = TOKENS * DMODEL; break;
        case 1: src = w0; dst = d0; n = DMODEL * DMODEL; break;
        case 2: src = w1; dst = d1; n = DMODEL * DMODEL; break;
        case 3: src = w2; dst = d2; n = DMODEL * DMODEL; break;
        case 4: src = w3; dst = d3; n = DMODEL * DMODEL; break;
        case 5: src = w4; dst = d4; n = DFF * DMODEL;    break;
        default:src = w5; dst = d5; n = DMODEL * DFF;    break;
    }
    int i = (blockIdx.x * 256 + threadIdx.x) * 4;
    if (i < n) {
        float4 v = *(const float4*)(src + i);
        *(__half2*)(dst + i)     = __floats2half2_rn(v.x, v.y);
        *(__half2*)(dst + i + 2) = __floats2half2_rn(v.z, v.w);
    }
}

// ---------------------------------------------------------------------------
// 128(M) x 128(N) x BK=64 fp16 GEMM, 3-stage cp.async, 2 CTAs/SM,
// single-barrier multistage loop. 128 threads / 4 warps (2m x 2n), warp
// tile 64x64 -> MMA:LDSM = 32:8 per ks-step.
// ---------------------------------------------------------------------------
#define HSTR   72
#define OPTILE (128 * HSTR)
#define NSTAGE 3
#define GEMM_SMEM (2 * NSTAGE * OPTILE * 2)      // 110592 B
#define GTHREADS 128

#define GEMM_IDS \
    const int tid = threadIdx.x; \
    const int wid = tid >> 5; \
    const int lid = tid & 31; \
    const int gid = lid >> 2; \
    const int tig = lid & 3; \
    const int wm0 = (wid & 1) * 64; \
    const int wn0 = (wid >> 1) * 64; \
    const int ldRow = tid >> 3; \
    const int ldC8  = (tid & 7) << 3; \
    const int a_moff = (lid & 7) + ((lid >> 3) & 1) * 8; \
    const int a_koff = (lid >> 4) * 8; \
    const int b_noff = (lid & 7) + ((lid >> 4) & 1) * 8; \
    const int b_koff = ((lid >> 3) & 1) * 8;

#define GEMM_SMEM_PTRS \
    extern __shared__ __half hsm[]; \
    uint32_t sA_u[NSTAGE], sB_u[NSTAGE]; \
    _Pragma("unroll") \
    for (int s_ = 0; s_ < NSTAGE; s_++) { \
        sA_u[s_] = smem_u32(hsm + s_ * OPTILE); \
        sB_u[s_] = smem_u32(hsm + (NSTAGE + s_) * OPTILE); \
    }

// 128 threads: each loads 8 x 16B for A and 8 x 16B for B (rows 0..127)
#define GEMM_LOAD_TILE(kt, buf, Ab, Bb, K) do { \
    const __half* Ak_ = (Ab) + (size_t)(kt) * 64; \
    const __half* Bk_ = (Bb) + (size_t)(kt) * 64; \
    _Pragma("unroll") \
    for (int it = 0; it < 8; it++) { \
        int row = ldRow + it * 16; \
        uint32_t so_ = (uint32_t)(row * HSTR + ldC8) * 2u; \
        CP_ASYNC16(sA_u[buf] + so_, Ak_ + (size_t)row * (K) + ldC8); \
        CP_ASYNC16(sB_u[buf] + so_, Bk_ + (size_t)row * (K) + ldC8); \
    } \
    CP_COMMIT(); \
} while (0)

#define GEMM_COMPUTE_TILE(buf, acc) do { \
    const uint32_t aB_ = sA_u[buf] + (uint32_t)((wm0 + a_moff) * HSTR + a_koff) * 2u; \
    const uint32_t bB_ = sB_u[buf] + (uint32_t)((wn0 + b_noff) * HSTR + b_koff) * 2u; \
    _Pragma("unroll") \
    for (int ks = 0; ks < 4; ks++) { \
        uint32_t a[4][4], b[4][4]; \
        _Pragma("unroll") \
        for (int fm = 0; fm < 4; fm++) \
            LDSM4(a[fm], aB_ + (uint32_t)(fm * 16 * HSTR) * 2u + ks * 32); \
        _Pragma("unroll") \
        for (int fn2 = 0; fn2 < 4; fn2++) \
            LDSM4(b[fn2], bB_ + (uint32_t)(fn2 * 16 * HSTR) * 2u + ks * 32); \
        _Pragma("unroll") \
        for (int fm = 0; fm < 4; fm++) \
            _Pragma("unroll") \
            for (int fn = 0; fn < 8; fn++) \
                MMA_F16(acc[fm][fn], \
                        a[fm][0], a[fm][1], a[fm][2], a[fm][3], \
                        b[fn >> 1][(fn & 1) * 2], b[fn >> 1][(fn & 1) * 2 + 1]); \
    } \
} while (0)

// Single-barrier multistage: wait(kt) -> barrier -> compute(kt) -> load(kt+2).
#define GEMM_MAINLOOP(Ab, Bb, K, acc) do { \
    const int KT_ = (K) >> 6; \
    GEMM_LOAD_TILE(0, 0, Ab, Bb, K); \
    GEMM_LOAD_TILE(1, 1, Ab, Bb, K); \
    for (int kt = 0; kt < KT_; kt++) { \
        if (kt + 1 < KT_) { CP_WAIT(1); } else { CP_WAIT(0); } \
        __syncthreads(); \
        GEMM_COMPUTE_TILE(kt % NSTAGE, acc); \
        if (kt + 2 < KT_) GEMM_LOAD_TILE(kt + 2, (kt + 2) % NSTAGE, Ab, Bb, K); \
    } \
} while (0)

// ---------------------------------------------------------------------------
// General GEMM:  C[M,N] = A[M,K] @ B[N,K]^T
// EPI: 0 = fp16, 3 = exact GELU -> fp16, 4 = fp32
// ---------------------------------------------------------------------------
template <int EPI>
__global__ __launch_bounds__(GTHREADS, 2)
void gemm128(const __half* __restrict__ A, const __half* __restrict__ B,
             void* __restrict__ Cv, int M, int N, int K)
{
    GEMM_SMEM_PTRS
    GEMM_IDS
    const int bm = blockIdx.y * 128;
    const int bn = blockIdx.x * 128;

    const __half* Ab = A + (size_t)bm * K;
    const __half* Bb = B + (size_t)bn * K;

    float acc[4][8][4];
#pragma unroll
    for (int i = 0; i < 4; i++)
#pragma unroll
        for (int j = 0; j < 8; j++)
#pragma unroll
            for (int r = 0; r < 4; r++) acc[i][j][r] = 0.f;

    GEMM_MAINLOOP(Ab, Bb, K, acc);

#pragma unroll
    for (int fm = 0; fm < 4; fm++) {
#pragma unroll
        for (int fn = 0; fn < 8; fn++) {
            float v[4];
#pragma unroll
            for (int r = 0; r < 4; r++) {
                float t = acc[fm][fn][r];
                if (EPI == 3) t = 0.5f * t * (1.f + erff(t * 0.70710678118654752f));
                v[r] = t;
            }
            const int row0 = bm + wm0 + fm * 16 + gid;
            const int col  = bn + wn0 + fn * 8 + tig * 2;
            if (EPI == 4) {
                float* C = (float*)Cv;
                *(float2*)(C + (size_t)row0 * N + col)       = make_float2(v[0], v[1]);
                *(float2*)(C + (size_t)(row0 + 8) * N + col) = make_float2(v[2], v[3]);
            } else {
                __half* C = (__half*)Cv;
                *(__half2*)(C + (size_t)row0 * N + col) =
                    __floats2half2_rn(v[0], v[1]);
                *(__half2*)(C + (size_t)(row0 + 8) * N + col) =
                    __floats2half2_rn(v[2], v[3]);
            }
        }
    }
}

// ---------------------------------------------------------------------------
// Fused QKV GEMM. grid.x = 24: weight w = blockIdx.x >> 3,
// bn = (blockIdx.x & 7) * 128. Epilogue: w=0 Q*QSCALE, w=1 K plain, w=2 V^T.
// ---------------------------------------------------------------------------
__global__ __launch_bounds__(GTHREADS, 2)
void gemm_qkv(const __half* __restrict__ A,
              const __half* __restrict__ Bq, const __half* __restrict__ Bk,
              const __half* __restrict__ Bv,
              __half* __restrict__ Cq, __half* __restrict__ Ck,
              __half* __restrict__ Cvt)
{
    GEMM_SMEM_PTRS
    GEMM_IDS
    const int K  = DMODEL;
    const int w  = blockIdx.x >> 3;
    const int bn = (blockIdx.x & 7) * 128;
    const int bm = blockIdx.y * 128;

    const __half* Bsel = (w == 0) ? Bq : (w == 1) ? Bk : Bv;
    const __half* Ab = A + (size_t)bm * K;
    const __half* Bb = Bsel + (size_t)bn * K;

    float acc[4][8][4];
#pragma unroll
    for (int i = 0; i < 4; i++)
#pragma unroll
        for (int j = 0; j < 8; j++)
#pragma unroll
            for (int r = 0; r < 4; r++) acc[i][j][r] = 0.f;

    GEMM_MAINLOOP(Ab, Bb, K, acc);

#pragma unroll
    for (int fm = 0; fm < 4; fm++) {
#pragma unroll
        for (int fn = 0; fn < 8; fn++) {
            const int row0 = bm + wm0 + fm * 16 + gid;
            const int col  = bn + wn0 + fn * 8 + tig * 2;
            float* v = acc[fm][fn];
            if (w == 0) {
                *(__half2*)(Cq + (size_t)row0 * DMODEL + col) =
                    __floats2half2_rn(v[0] * QSCALE, v[1] * QSCALE);
                *(__half2*)(Cq + (size_t)(row0 + 8) * DMODEL + col) =
                    __floats2half2_rn(v[2] * QSCALE, v[3] * QSCALE);
            } else if (w == 1) {
                *(__half2*)(Ck + (size_t)row0 * DMODEL + col) =
                    __floats2half2_rn(v[0], v[1]);
                *(__half2*)(Ck + (size_t)(row0 + 8) * DMODEL + col) =
                    __floats2half2_rn(v[2], v[3]);
            } else {
#pragma unroll
                for (int ri = 0; ri < 2; ri++) {
#pragma unroll
                    for (int ci = 0; ci < 2; ci++) {
                        int r = row0 + ri * 8;
                        int c = col + ci;
                        int bb = r >> 11, ss = r & 2047;
                        int hh = c >> 6,  dd = c & 63;
                        Cvt[(((size_t)(bb * 16 + hh)) * 64 + dd) * SEQ + ss] =
                            __float2half(v[ri * 2 + ci]);
                    }
                }
            }
        }
    }
}

// ---------------------------------------------------------------------------
// Flash attention (unchanged from R12): fp16 mma + ldmatrix, Q frags in regs,
// 3-stage KV, single barrier per KV tile, 2 CTAs/SM, log2-domain softmax.
// ---------------------------------------------------------------------------
#define FQS 72
#define KVSTG 3
#define FLASHH_SMEM ((128 * FQS + 2 * KVSTG * 64 * FQS) * 2)   // 73728 B

__global__ __launch_bounds__(256, 2)
void flash_h(const __half* __restrict__ Q, const __half* __restrict__ K,
             const __half* __restrict__ Vt, __half* __restrict__ Oa)
{
    extern __shared__ __half fsh[];
    __half* Qs = fsh;
    const uint32_t qs_u = smem_u32(Qs);
    uint32_t ks_u[KVSTG], vs_u[KVSTG];
#pragma unroll
    for (int s_ = 0; s_ < KVSTG; s_++) {
        ks_u[s_] = smem_u32(Qs + 128 * FQS + s_ * 64 * FQS);
        vs_u[s_] = smem_u32(Qs + 128 * FQS + (KVSTG + s_) * 64 * FQS);
    }

    const int tid = threadIdx.x;
    const int wid = tid >> 5;
    const int lid = tid & 31;
    const int gid = lid >> 2;
    const int tig = lid & 3;
    const int q0  = blockIdx.x * 128;
    const int bh  = blockIdx.y;
    const int b   = bh >> 4;
    const int h   = bh & 15;
    const int m0  = wid * 16;

    const int a_moff = (lid & 7) + ((lid >> 3) & 1) * 8;
    const int a_koff = (lid >> 4) * 8;
    const int b_noff = (lid & 7) + ((lid >> 4) & 1) * 8;
    const int b_koff = ((lid >> 3) & 1) * 8;

    const size_t base = (size_t)b * SEQ * DMODEL + h * DK;
    const __half* Qb = Q + base;
    const __half* Kb = K + base;
    const __half* Vb = Vt + ((size_t)(b * 16 + h)) * 64 * SEQ;
    __half*       Ob = Oa + base;

    // Q tile (group 0)
#pragma unroll
    for (int it = 0; it < 4; it++) {
        int s   = tid + it * 256;
        int row = s >> 3;
        int c8  = (s & 7) << 3;
        CP_ASYNC16(qs_u + (uint32_t)(row * FQS + c8) * 2u,
                   Qb + (size_t)(q0 + row) * DMODEL + c8);
    }
    CP_COMMIT();

    auto load_kv = [&](int kt, int buf) {
        const __half* Kt  = Kb + (size_t)kt * 64 * DMODEL;
        const __half* Vtt = Vb + kt * 64;
#pragma unroll
        for (int it = 0; it < 2; it++) {
            int s   = tid + it * 256;
            int row = s >> 3;
            int c8  = (s & 7) << 3;
            CP_ASYNC16(ks_u[buf] + (uint32_t)(row * FQS + c8) * 2u,
                       Kt + (size_t)row * DMODEL + c8);
            CP_ASYNC16(vs_u[buf] + (uint32_t)(row * FQS + c8) * 2u,
                       Vtt + (size_t)row * SEQ + c8);
        }
        CP_COMMIT();
    };

    load_kv(0, 0);      // group 1
    load_kv(1, 1);      // group 2

    // hoist Q fragments (wait: Q group done; kv0/kv1 may pend)
    CP_WAIT(2);
    __syncthreads();
    uint32_t qf[4][4];
    {
        const uint32_t qB = qs_u + (uint32_t)((m0 + a_moff) * FQS + a_koff) * 2u;
#pragma unroll
        for (int kf = 0; kf < 4; kf++)
            LDSM4(qf[kf], qB + kf * 32);
    }

    float m[2] = { -1e30f, -1e30f };
    float l[2] = { 0.f, 0.f };
    float o[8][4];
#pragma unroll
    for (int d = 0; d < 8; d++)
#pragma unroll
        for (int r = 0; r < 4; r++) o[d][r] = 0.f;

    const int NT = SEQ / 64;

    for (int kt = 0; kt < NT; kt++) {
        const int buf = kt % KVSTG;
        if (kt + 1 < NT) { CP_WAIT(1); } else { CP_WAIT(0); }
        __syncthreads();

        const uint32_t kB = ks_u[buf] + (uint32_t)(b_noff * FQS + b_koff) * 2u;
        const uint32_t vB = vs_u[buf] + (uint32_t)(b_noff * FQS + b_koff) * 2u;

        // ---- S = Q @ K^T (log2-domain scores) ----
        float s[8][4];
#pragma unroll
        for (int nf = 0; nf < 8; nf++)
#pragma unroll
            for (int r = 0; r < 4; r++) s[nf][r] = 0.f;

#pragma unroll
        for (int kf = 0; kf < 4; kf++) {
#pragma unroll
            for (int fn2 = 0; fn2 < 4; fn2++) {
                uint32_t kb[4];
                LDSM4(kb, kB + (uint32_t)(fn2 * 16 * FQS) * 2u + kf * 32);
                MMA_F16(s[2 * fn2],     qf[kf][0], qf[kf][1], qf[kf][2], qf[kf][3],
                        kb[0], kb[1]);
                MMA_F16(s[2 * fn2 + 1], qf[kf][0], qf[kf][1], qf[kf][2], qf[kf][3],
                        kb[2], kb[3]);
            }
        }

        // ---- online softmax (base-2) ----
        float mx0 = -1e30f, mx1 = -1e30f;
#pragma unroll
        for (int nf = 0; nf < 8; nf++) {
            mx0 = fmaxf(mx0, fmaxf(s[nf][0], s[nf][1]));
            mx1 = fmaxf(mx1, fmaxf(s[nf][2], s[nf][3]));
        }
        mx0 = fmaxf(mx0, __shfl_xor_sync(0xffffffffu, mx0, 1));
        mx0 = fmaxf(mx0, __shfl_xor_sync(0xffffffffu, mx0, 2));
        mx1 = fmaxf(mx1, __shfl_xor_sync(0xffffffffu, mx1, 1));
        mx1 = fmaxf(mx1, __shfl_xor_sync(0xffffffffu, mx1, 2));

        const float mn0 = fmaxf(m[0], mx0);
        const float mn1 = fmaxf(m[1], mx1);
        const float al0 = ex2f(m[0] - mn0);
        const float al1 = ex2f(m[1] - mn1);

        float sum0 = 0.f, sum1 = 0.f;
#pragma unroll
        for (int nf = 0; nf < 8; nf++) {
            s[nf][0] = ex2f(s[nf][0] - mn0);
            s[nf][1] = ex2f(s[nf][1] - mn0);
            s[nf][2] = ex2f(s[nf][2] - mn1);
            s[nf][3] = ex2f(s[nf][3] - mn1);
            sum0 += s[nf][0] + s[nf][1];
            sum1 += s[nf][2] + s[nf][3];
        }
        sum0 += __shfl_xor_sync(0xffffffffu, sum0, 1);
        sum0 += __shfl_xor_sync(0xffffffffu, sum0, 2);
        sum1 += __shfl_xor_sync(0xffffffffu, sum1, 1);
        sum1 += __shfl_xor_sync(0xffffffffu, sum1, 2);

        l[0] = l[0] * al0 + sum0;
        l[1] = l[1] * al1 + sum1;
        m[0] = mn0;
        m[1] = mn1;

#pragma unroll
        for (int d = 0; d < 8; d++) {
            o[d][0] *= al0; o[d][1] *= al0;
            o[d][2] *= al1; o[d][3] *= al1;
        }

        // ---- O += P @ V ----
#pragma unroll
        for (int c = 0; c < 4; c++) {
            uint32_t a0 = pack_h2(s[2*c][0],   s[2*c][1]);
            uint32_t a1 = pack_h2(s[2*c][2],   s[2*c][3]);
            uint32_t a2 = pack_h2(s[2*c+1][0], s[2*c+1][1]);
            uint32_t a3 = pack_h2(s[2*c+1][2], s[2*c+1][3]);
#pragma unroll
            for (int fn2 = 0; fn2 < 4; fn2++) {
                uint32_t vb[4];
                LDSM4(vb, vB + (uint32_t)(fn2 * 16 * FQS) * 2u + c * 32);
                MMA_F16(o[2 * fn2],     a0, a1, a2, a3, vb[0], vb[1]);
                MMA_F16(o[2 * fn2 + 1], a0, a1, a2, a3, vb[2], vb[3]);
            }
        }

        // prefetch kt+2 into stage (kt+2)%3 == (kt-1)%3 (safe: barrier above)
        if (kt + 2 < NT) load_kv(kt + 2, (kt + 2) % KVSTG);
    }

    const float inv0 = 1.f / l[0];
    const float inv1 = 1.f / l[1];
    const int row0 = q0 + m0 + gid;
#pragma unroll
    for (int d = 0; d < 8; d++) {
        const int col = d * 8 + tig * 2;
        *(__half2*)(Ob + (size_t)row0 * DMODEL + col) =
            __floats2half2_rn(o[d][0] * inv0, o[d][1] * inv0);
        *(__half2*)(Ob + (size_t)(row0 + 8) * DMODEL + col) =
            __floats2half2_rn(o[d][2] * inv1, o[d][3] * inv1);
    }
}

// ---------------------------------------------------------------------------
// y = LayerNorm(a + b) * gamma + beta; dual output (fp32 + fp16)
// ---------------------------------------------------------------------------
__global__ __launch_bounds__(256)
void add_ln2(const float* __restrict__ a, const float* __restrict__ b,
             const float* __restrict__ gamma, const float* __restrict__ beta,
             float* __restrict__ y, __half* __restrict__ yh)
{
    const int row = blockIdx.x;
    const int tid = threadIdx.x;
    __shared__ float rs[256], rq[256];

    float4 va = ((const float4*)(a + (size_t)row * DMODEL))[tid];
    float4 vb = ((const float4*)(b + (size_t)row * DMODEL))[tid];
    float s0 = va.x + vb.x, s1 = va.y + vb.y, s2 = va.z + vb.z, s3 = va.w + vb.w;

    rs[tid] = s0 + s1 + s2 + s3;
    rq[tid] = s0 * s0 + s1 * s1 + s2 * s2 + s3 * s3;
    __syncthreads();
#pragma unroll
    for (int off = 128; off > 0; off >>= 1) {
        if (tid < off) { rs[tid] += rs[tid + off]; rq[tid] += rq[tid + off]; }
        __syncthreads();
    }
    const float mu   = rs[0] * (1.f / DMODEL);
    const float var  = rq[0] * (1.f / DMODEL) - mu * mu;
    const float rinv = rsqrtf(var + 1e-5f);

    float4 g  = ((const float4*)gamma)[tid];
    float4 be = ((const float4*)beta)[tid];
    float4 out;
    out.x = (s0 - mu) * rinv * g.x + be.x;
    out.y = (s1 - mu) * rinv * g.y + be.y;
    out.z = (s2 - mu) * rinv * g.z + be.z;
    out.w = (s3 - mu) * rinv * g.w + be.w;
    ((float4*)(y + (size_t)row * DMODEL))[tid] = out;

    __half* hp = yh + (size_t)row * DMODEL + tid * 4;
    *(__half2*)(hp)     = __floats2half2_rn(out.x, out.y);
    *(__half2*)(hp + 2) = __floats2half2_rn(out.z, out.w);
}

// ---------------------------------------------------------------------------
// launch
// ---------------------------------------------------------------------------
extern "C" void kernel_launch(void* const* d_in, const int* in_sizes, int n_in,
                              void* d_out, int out_size)
{
    const float* x  = (const float*)d_in[0];
    const float* Wq = (const float*)d_in[1];
    const float* Wk = (const float*)d_in[2];
    const float* Wv = (const float*)d_in[3];
    const float* Wo = (const float*)d_in[4];
    const float* W1 = (const float*)d_in[5];
    const float* W2 = (const float*)d_in[6];
    const float* g1 = (const float*)d_in[7];
    const float* b1 = (const float*)d_in[8];
    const float* g2 = (const float*)d_in[9];
    const float* b2 = (const float*)d_in[10];
    float* out = (float*)d_out;

    __half *px, *pwq, *pwk, *pwv, *pwo, *pw1, *pw2;
    __half *pq, *pk, *pvt, *pattn, *px1h, *pff;
    float *pproj, *px1;
    cudaGetSymbolAddress((void**)&px,   hx);
    cudaGetSymbolAddress((void**)&pwq,  hWq);
    cudaGetSymbolAddress((void**)&pwk,  hWk);
    cudaGetSymbolAddress((void**)&pwv,  hWv);
    cudaGetSymbolAddress((void**)&pwo,  hWo);
    cudaGetSymbolAddress((void**)&pw1,  hW1);
    cudaGetSymbolAddress((void**)&pw2,  hW2);
    cudaGetSymbolAddress((void**)&pq,   hq);
    cudaGetSymbolAddress((void**)&pk,   hk);
    cudaGetSymbolAddress((void**)&pvt,  hvt);
    cudaGetSymbolAddress((void**)&pattn,hattn);
    cudaGetSymbolAddress((void**)&px1h, hx1);
    cudaGetSymbolAddress((void**)&pff,  hff);
    cudaGetSymbolAddress((void**)&pproj,g_proj);
    cudaGetSymbolAddress((void**)&px1,  g_x1);

    cudaFuncSetAttribute(gemm128<0>, cudaFuncAttributeMaxDynamicSharedMemorySize, GEMM_SMEM);
    cudaFuncSetAttribute(gemm128<3>, cudaFuncAttributeMaxDynamicSharedMemorySize, GEMM_SMEM);
    cudaFuncSetAttribute(gemm128<4>, cudaFuncAttributeMaxDynamicSharedMemorySize, GEMM_SMEM);
    cudaFuncSetAttribute(gemm_qkv,   cudaFuncAttributeMaxDynamicSharedMemorySize, GEMM_SMEM);
    cudaFuncSetAttribute(flash_h,    cudaFuncAttributeMaxDynamicSharedMemorySize, FLASHH_SMEM);

    dim3 gblk(GTHREADS);
    dim3 blk(256);

    // fp32 -> fp16, single launch
    f2h_all<<<dim3(TOKENS * DMODEL / 1024, 7), blk>>>(
        x, px, Wq, pwq, Wk, pwk, Wv, pwv, Wo, pwo, W1, pw1, W2, pw2);

    // fused QKV projections (grid.x = 3 weights * 8 n-tiles)
    gemm_qkv<<<dim3(24, TOKENS / 128), gblk, GEMM_SMEM>>>(
        px, pwq, pwk, pwv, pq, pk, pvt);

    // attention
    dim3 gattn(SEQ / 128, 2 * NHEADS);
    flash_h<<<gattn, blk, FLASHH_SMEM>>>(pq, pk, pvt, pattn);

    // output projection + residual + LN1
    gemm128<4><<<dim3(DMODEL / 128, TOKENS / 128), gblk, GEMM_SMEM>>>(
        pattn, pwo, pproj, TOKENS, DMODEL, DMODEL);
    add_ln2<<<TOKENS, 256>>>(x, pproj, g1, b1, px1, px1h);

    // FF1 (+GELU), FF2, residual + LN2
    gemm128<3><<<dim3(DFF / 128, TOKENS / 128), gblk, GEMM_SMEM>>>(
        px1h, pw1, pff, TOKENS, DFF, DMODEL);
    gemm128<4><<<dim3(DMODEL / 128, TOKENS / 128), gblk, GEMM_SMEM>>>(
        pff, pw2, pproj, TOKENS, DMODEL, DFF);
    add_ln2<<<TOKENS, 256>>>(px1, pproj, g2, b2, out, px1h);
}

// round 17
// speedup vs baseline: 1.1173x; 1.0185x over previous
#include <cuda_runtime.h>
#include <cuda_fp16.h>
#include <math.h>
#include <cstdint>

// ---------------------------------------------------------------------------
// Problem constants
// ---------------------------------------------------------------------------
#define TOKENS 4096        // B*S = 2*2048
#define DMODEL 1024
#define DFF    4096
#define NHEADS 16
#define DK     64
#define SEQ    2048

// Q pre-scale: 1/sqrt(64) * log2(e) -> softmax computed with ex2
#define QSCALE 0.18033688011112042f

// ---------------------------------------------------------------------------
// Scratch (device globals)
// ---------------------------------------------------------------------------
__device__ __half hx   [TOKENS * DMODEL];
__device__ __half hWq  [DMODEL * DMODEL];
__device__ __half hWk  [DMODEL * DMODEL];
__device__ __half hWv  [DMODEL * DMODEL];
__device__ __half hWo  [DMODEL * DMODEL];
__device__ __half hW1  [DFF * DMODEL];
__device__ __half hW2  [DMODEL * DFF];
__device__ __half hq   [TOKENS * DMODEL];   // pre-scaled by QSCALE
__device__ __half hk   [TOKENS * DMODEL];
__device__ __half hvt  [TOKENS * DMODEL];   // V transposed: [b][h][d][s]
__device__ __half hattn[TOKENS * DMODEL];
__device__ __half hx1  [TOKENS * DMODEL];
__device__ __half hff  [TOKENS * DFF];
__device__ __half hproj[TOKENS * DMODEL];   // fp16 projection intermediate
__device__ float  g_x1 [TOKENS * DMODEL];

// ---------------------------------------------------------------------------
// Helpers
// ---------------------------------------------------------------------------
__device__ __forceinline__ uint32_t smem_u32(const void* p) {
    uint32_t a;
    asm("{ .reg .u64 t; cvta.to.shared.u64 t, %1; cvt.u32.u64 %0, t; }"
        : "=r"(a) : "l"(p));
    return a;
}

__device__ __forceinline__ float ex2f(float x) {
    float r;
    asm("ex2.approx.f32 %0, %1;" : "=f"(r) : "f"(x));
    return r;
}

#define CP_ASYNC16(dst_u32, src_ptr) \
    asm volatile("cp.async.cg.shared.global [%0], [%1], 16;" \
        :: "r"(dst_u32), "l"(src_ptr))
#define CP_COMMIT() asm volatile("cp.async.commit_group;")
#define CP_WAIT(n)  asm volatile("cp.async.wait_group %0;" :: "n"(n))

#define MMA_F16(c, a0, a1, a2, a3, b0, b1) \
    asm volatile("mma.sync.aligned.m16n8k16.row.col.f32.f16.f16.f32 " \
        "{%0,%1,%2,%3}, {%4,%5,%6,%7}, {%8,%9}, {%0,%1,%2,%3};" \
        : "+f"((c)[0]), "+f"((c)[1]), "+f"((c)[2]), "+f"((c)[3]) \
        : "r"(a0), "r"(a1), "r"(a2), "r"(a3), "r"(b0), "r"(b1))

#define LDSM4(r, addr) \
    asm volatile("ldmatrix.sync.aligned.m8n8.x4.shared.b16 {%0,%1,%2,%3}, [%4];" \
        : "=r"((r)[0]), "=r"((r)[1]), "=r"((r)[2]), "=r"((r)[3]) : "r"(addr))

__device__ __forceinline__ uint32_t pack_h2(float lo, float hi) {
    __half2 h = __floats2half2_rn(lo, hi);
    return *reinterpret_cast<uint32_t*>(&h);
}

// ---------------------------------------------------------------------------
// fp32 -> fp16 conversion, all tensors in one launch (grid.y selects tensor)
// ---------------------------------------------------------------------------
__global__ __launch_bounds__(256)
void f2h_all(const float* x,  __half* dx,
             const float* w0, __half* d0, const float* w1, __half* d1,
             const float* w2, __half* d2, const float* w3, __half* d3,
             const float* w4, __half* d4, const float* w5, __half* d5)
{
    const float* src; __half* dst; int n;
    switch (blockIdx.y) {
        case 0: src = x;  dst = dx; n = TOKENS * DMODEL; break;
        case 1: src = w0; dst = d0; n = DMODEL * DMODEL; break;
        case 2: src = w1; dst = d1; n = DMODEL * DMODEL; break;
        case 3: src = w2; dst = d2; n = DMODEL * DMODEL; break;
        case 4: src = w3; dst = d3; n = DMODEL * DMODEL; break;
        case 5: src = w4; dst = d4; n = DFF * DMODEL;    break;
        default:src = w5; dst = d5; n = DMODEL * DFF;    break;
    }
    int i = (blockIdx.x * 256 + threadIdx.x) * 4;
    if (i < n) {
        float4 v = *(const float4*)(src + i);
        *(__half2*)(dst + i)     = __floats2half2_rn(v.x, v.y);
        *(__half2*)(dst + i + 2) = __floats2half2_rn(v.z, v.w);
    }
}

// ---------------------------------------------------------------------------
// 128(M) x 128(N) x BK=64 fp16 GEMM, 3-stage cp.async, 2 CTAs/SM,
// single-barrier multistage loop. 128 threads / 4 warps (2m x 2n), warp
// tile 64x64 (R13 proven config).
// ---------------------------------------------------------------------------
#define HSTR   72
#define OPTILE (128 * HSTR)
#define NSTAGE 3
#define GEMM_SMEM (2 * NSTAGE * OPTILE * 2)      // 110592 B
#define GTHREADS 128

#define GEMM_IDS \
    const int tid = threadIdx.x; \
    const int wid = tid >> 5; \
    const int lid = tid & 31; \
    const int gid = lid >> 2; \
    const int tig = lid & 3; \
    const int wm0 = (wid & 1) * 64; \
    const int wn0 = (wid >> 1) * 64; \
    const int ldRow = tid >> 3; \
    const int ldC8  = (tid & 7) << 3; \
    const int a_moff = (lid & 7) + ((lid >> 3) & 1) * 8; \
    const int a_koff = (lid >> 4) * 8; \
    const int b_noff = (lid & 7) + ((lid >> 4) & 1) * 8; \
    const int b_koff = ((lid >> 3) & 1) * 8;

#define GEMM_SMEM_PTRS \
    extern __shared__ __half hsm[]; \
    uint32_t sA_u[NSTAGE], sB_u[NSTAGE]; \
    _Pragma("unroll") \
    for (int s_ = 0; s_ < NSTAGE; s_++) { \
        sA_u[s_] = smem_u32(hsm + s_ * OPTILE); \
        sB_u[s_] = smem_u32(hsm + (NSTAGE + s_) * OPTILE); \
    }

// 128 threads: each loads 8 x 16B for A and 8 x 16B for B (rows 0..127)
#define GEMM_LOAD_TILE(kt, buf, Ab, Bb, K) do { \
    const __half* Ak_ = (Ab) + (size_t)(kt) * 64; \
    const __half* Bk_ = (Bb) + (size_t)(kt) * 64; \
    _Pragma("unroll") \
    for (int it = 0; it < 8; it++) { \
        int row = ldRow + it * 16; \
        uint32_t so_ = (uint32_t)(row * HSTR + ldC8) * 2u; \
        CP_ASYNC16(sA_u[buf] + so_, Ak_ + (size_t)row * (K) + ldC8); \
        CP_ASYNC16(sB_u[buf] + so_, Bk_ + (size_t)row * (K) + ldC8); \
    } \
    CP_COMMIT(); \
} while (0)

#define GEMM_COMPUTE_TILE(buf, acc) do { \
    const uint32_t aB_ = sA_u[buf] + (uint32_t)((wm0 + a_moff) * HSTR + a_koff) * 2u; \
    const uint32_t bB_ = sB_u[buf] + (uint32_t)((wn0 + b_noff) * HSTR + b_koff) * 2u; \
    _Pragma("unroll") \
    for (int ks = 0; ks < 4; ks++) { \
        uint32_t a[4][4], b[4][4]; \
        _Pragma("unroll") \
        for (int fm = 0; fm < 4; fm++) \
            LDSM4(a[fm], aB_ + (uint32_t)(fm * 16 * HSTR) * 2u + ks * 32); \
        _Pragma("unroll") \
        for (int fn2 = 0; fn2 < 4; fn2++) \
            LDSM4(b[fn2], bB_ + (uint32_t)(fn2 * 16 * HSTR) * 2u + ks * 32); \
        _Pragma("unroll") \
        for (int fm = 0; fm < 4; fm++) \
            _Pragma("unroll") \
            for (int fn = 0; fn < 8; fn++) \
                MMA_F16(acc[fm][fn], \
                        a[fm][0], a[fm][1], a[fm][2], a[fm][3], \
                        b[fn >> 1][(fn & 1) * 2], b[fn >> 1][(fn & 1) * 2 + 1]); \
    } \
} while (0)

// Single-barrier multistage: wait(kt) -> barrier -> compute(kt) -> load(kt+2).
#define GEMM_MAINLOOP(Ab, Bb, K, acc) do { \
    const int KT_ = (K) >> 6; \
    GEMM_LOAD_TILE(0, 0, Ab, Bb, K); \
    GEMM_LOAD_TILE(1, 1, Ab, Bb, K); \
    for (int kt = 0; kt < KT_; kt++) { \
        if (kt + 1 < KT_) { CP_WAIT(1); } else { CP_WAIT(0); } \
        __syncthreads(); \
        GEMM_COMPUTE_TILE(kt % NSTAGE, acc); \
        if (kt + 2 < KT_) GEMM_LOAD_TILE(kt + 2, (kt + 2) % NSTAGE, Ab, Bb, K); \
    } \
} while (0)

// ---------------------------------------------------------------------------
// General GEMM:  C[M,N] = A[M,K] @ B[N,K]^T   (fp16 out)
// EPI: 0 = fp16, 3 = exact GELU -> fp16
// ---------------------------------------------------------------------------
template <int EPI>
__global__ __launch_bounds__(GTHREADS, 2)
void gemm128(const __half* __restrict__ A, const __half* __restrict__ B,
             __half* __restrict__ C, int M, int N, int K)
{
    GEMM_SMEM_PTRS
    GEMM_IDS
    const int bm = blockIdx.y * 128;
    const int bn = blockIdx.x * 128;

    const __half* Ab = A + (size_t)bm * K;
    const __half* Bb = B + (size_t)bn * K;

    float acc[4][8][4];
#pragma unroll
    for (int i = 0; i < 4; i++)
#pragma unroll
        for (int j = 0; j < 8; j++)
#pragma unroll
            for (int r = 0; r < 4; r++) acc[i][j][r] = 0.f;

    GEMM_MAINLOOP(Ab, Bb, K, acc);

#pragma unroll
    for (int fm = 0; fm < 4; fm++) {
#pragma unroll
        for (int fn = 0; fn < 8; fn++) {
            float v[4];
#pragma unroll
            for (int r = 0; r < 4; r++) {
                float t = acc[fm][fn][r];
                if (EPI == 3) t = 0.5f * t * (1.f + erff(t * 0.70710678118654752f));
                v[r] = t;
            }
            const int row0 = bm + wm0 + fm * 16 + gid;
            const int col  = bn + wn0 + fn * 8 + tig * 2;
            *(__half2*)(C + (size_t)row0 * N + col) =
                __floats2half2_rn(v[0], v[1]);
            *(__half2*)(C + (size_t)(row0 + 8) * N + col) =
                __floats2half2_rn(v[2], v[3]);
        }
    }
}

// ---------------------------------------------------------------------------
// Fused QKV GEMM. grid.x = 24: weight w = blockIdx.x >> 3,
// bn = (blockIdx.x & 7) * 128. Epilogue: w=0 Q*QSCALE, w=1 K plain, w=2 V^T.
// ---------------------------------------------------------------------------
__global__ __launch_bounds__(GTHREADS, 2)
void gemm_qkv(const __half* __restrict__ A,
              const __half* __restrict__ Bq, const __half* __restrict__ Bk,
              const __half* __restrict__ Bv,
              __half* __restrict__ Cq, __half* __restrict__ Ck,
              __half* __restrict__ Cvt)
{
    GEMM_SMEM_PTRS
    GEMM_IDS
    const int K  = DMODEL;
    const int w  = blockIdx.x >> 3;
    const int bn = (blockIdx.x & 7) * 128;
    const int bm = blockIdx.y * 128;

    const __half* Bsel = (w == 0) ? Bq : (w == 1) ? Bk : Bv;
    const __half* Ab = A + (size_t)bm * K;
    const __half* Bb = Bsel + (size_t)bn * K;

    float acc[4][8][4];
#pragma unroll
    for (int i = 0; i < 4; i++)
#pragma unroll
        for (int j = 0; j < 8; j++)
#pragma unroll
            for (int r = 0; r < 4; r++) acc[i][j][r] = 0.f;

    GEMM_MAINLOOP(Ab, Bb, K, acc);

#pragma unroll
    for (int fm = 0; fm < 4; fm++) {
#pragma unroll
        for (int fn = 0; fn < 8; fn++) {
            const int row0 = bm + wm0 + fm * 16 + gid;
            const int col  = bn + wn0 + fn * 8 + tig * 2;
            float* v = acc[fm][fn];
            if (w == 0) {
                *(__half2*)(Cq + (size_t)row0 * DMODEL + col) =
                    __floats2half2_rn(v[0] * QSCALE, v[1] * QSCALE);
                *(__half2*)(Cq + (size_t)(row0 + 8) * DMODEL + col) =
                    __floats2half2_rn(v[2] * QSCALE, v[3] * QSCALE);
            } else if (w == 1) {
                *(__half2*)(Ck + (size_t)row0 * DMODEL + col) =
                    __floats2half2_rn(v[0], v[1]);
                *(__half2*)(Ck + (size_t)(row0 + 8) * DMODEL + col) =
                    __floats2half2_rn(v[2], v[3]);
            } else {
#pragma unroll
                for (int ri = 0; ri < 2; ri++) {
#pragma unroll
                    for (int ci = 0; ci < 2; ci++) {
                        int r = row0 + ri * 8;
                        int c = col + ci;
                        int bb = r >> 11, ss = r & 2047;
                        int hh = c >> 6,  dd = c & 63;
                        Cvt[(((size_t)(bb * 16 + hh)) * 64 + dd) * SEQ + ss] =
                            __float2half(v[ri * 2 + ci]);
                    }
                }
            }
        }
    }
}

// ---------------------------------------------------------------------------
// Flash attention (unchanged from R13): fp16 mma + ldmatrix, Q frags in regs,
// 3-stage KV, single barrier per KV tile, 2 CTAs/SM, log2-domain softmax.
// ---------------------------------------------------------------------------
#define FQS 72
#define KVSTG 3
#define FLASHH_SMEM ((128 * FQS + 2 * KVSTG * 64 * FQS) * 2)   // 73728 B

__global__ __launch_bounds__(256, 2)
void flash_h(const __half* __restrict__ Q, const __half* __restrict__ K,
             const __half* __restrict__ Vt, __half* __restrict__ Oa)
{
    extern __shared__ __half fsh[];
    __half* Qs = fsh;
    const uint32_t qs_u = smem_u32(Qs);
    uint32_t ks_u[KVSTG], vs_u[KVSTG];
#pragma unroll
    for (int s_ = 0; s_ < KVSTG; s_++) {
        ks_u[s_] = smem_u32(Qs + 128 * FQS + s_ * 64 * FQS);
        vs_u[s_] = smem_u32(Qs + 128 * FQS + (KVSTG + s_) * 64 * FQS);
    }

    const int tid = threadIdx.x;
    const int wid = tid >> 5;
    const int lid = tid & 31;
    const int gid = lid >> 2;
    const int tig = lid & 3;
    const int q0  = blockIdx.x * 128;
    const int bh  = blockIdx.y;
    const int b   = bh >> 4;
    const int h   = bh & 15;
    const int m0  = wid * 16;

    const int a_moff = (lid & 7) + ((lid >> 3) & 1) * 8;
    const int a_koff = (lid >> 4) * 8;
    const int b_noff = (lid & 7) + ((lid >> 4) & 1) * 8;
    const int b_koff = ((lid >> 3) & 1) * 8;

    const size_t base = (size_t)b * SEQ * DMODEL + h * DK;
    const __half* Qb = Q + base;
    const __half* Kb = K + base;
    const __half* Vb = Vt + ((size_t)(b * 16 + h)) * 64 * SEQ;
    __half*       Ob = Oa + base;

    // Q tile (group 0)
#pragma unroll
    for (int it = 0; it < 4; it++) {
        int s   = tid + it * 256;
        int row = s >> 3;
        int c8  = (s & 7) << 3;
        CP_ASYNC16(qs_u + (uint32_t)(row * FQS + c8) * 2u,
                   Qb + (size_t)(q0 + row) * DMODEL + c8);
    }
    CP_COMMIT();

    auto load_kv = [&](int kt, int buf) {
        const __half* Kt  = Kb + (size_t)kt * 64 * DMODEL;
        const __half* Vtt = Vb + kt * 64;
#pragma unroll
        for (int it = 0; it < 2; it++) {
            int s   = tid + it * 256;
            int row = s >> 3;
            int c8  = (s & 7) << 3;
            CP_ASYNC16(ks_u[buf] + (uint32_t)(row * FQS + c8) * 2u,
                       Kt + (size_t)row * DMODEL + c8);
            CP_ASYNC16(vs_u[buf] + (uint32_t)(row * FQS + c8) * 2u,
                       Vtt + (size_t)row * SEQ + c8);
        }
        CP_COMMIT();
    };

    load_kv(0, 0);      // group 1
    load_kv(1, 1);      // group 2

    // hoist Q fragments (wait: Q group done; kv0/kv1 may pend)
    CP_WAIT(2);
    __syncthreads();
    uint32_t qf[4][4];
    {
        const uint32_t qB = qs_u + (uint32_t)((m0 + a_moff) * FQS + a_koff) * 2u;
#pragma unroll
        for (int kf = 0; kf < 4; kf++)
            LDSM4(qf[kf], qB + kf * 32);
    }

    float m[2] = { -1e30f, -1e30f };
    float l[2] = { 0.f, 0.f };
    float o[8][4];
#pragma unroll
    for (int d = 0; d < 8; d++)
#pragma unroll
        for (int r = 0; r < 4; r++) o[d][r] = 0.f;

    const int NT = SEQ / 64;

    for (int kt = 0; kt < NT; kt++) {
        const int buf = kt % KVSTG;
        if (kt + 1 < NT) { CP_WAIT(1); } else { CP_WAIT(0); }
        __syncthreads();

        const uint32_t kB = ks_u[buf] + (uint32_t)(b_noff * FQS + b_koff) * 2u;
        const uint32_t vB = vs_u[buf] + (uint32_t)(b_noff * FQS + b_koff) * 2u;

        // ---- S = Q @ K^T (log2-domain scores) ----
        float s[8][4];
#pragma unroll
        for (int nf = 0; nf < 8; nf++)
#pragma unroll
            for (int r = 0; r < 4; r++) s[nf][r] = 0.f;

#pragma unroll
        for (int kf = 0; kf < 4; kf++) {
#pragma unroll
            for (int fn2 = 0; fn2 < 4; fn2++) {
                uint32_t kb[4];
                LDSM4(kb, kB + (uint32_t)(fn2 * 16 * FQS) * 2u + kf * 32);
                MMA_F16(s[2 * fn2],     qf[kf][0], qf[kf][1], qf[kf][2], qf[kf][3],
                        kb[0], kb[1]);
                MMA_F16(s[2 * fn2 + 1], qf[kf][0], qf[kf][1], qf[kf][2], qf[kf][3],
                        kb[2], kb[3]);
            }
        }

        // ---- online softmax (base-2) ----
        float mx0 = -1e30f, mx1 = -1e30f;
#pragma unroll
        for (int nf = 0; nf < 8; nf++) {
            mx0 = fmaxf(mx0, fmaxf(s[nf][0], s[nf][1]));
            mx1 = fmaxf(mx1, fmaxf(s[nf][2], s[nf][3]));
        }
        mx0 = fmaxf(mx0, __shfl_xor_sync(0xffffffffu, mx0, 1));
        mx0 = fmaxf(mx0, __shfl_xor_sync(0xffffffffu, mx0, 2));
        mx1 = fmaxf(mx1, __shfl_xor_sync(0xffffffffu, mx1, 1));
        mx1 = fmaxf(mx1, __shfl_xor_sync(0xffffffffu, mx1, 2));

        const float mn0 = fmaxf(m[0], mx0);
        const float mn1 = fmaxf(m[1], mx1);
        const float al0 = ex2f(m[0] - mn0);
        const float al1 = ex2f(m[1] - mn1);

        float sum0 = 0.f, sum1 = 0.f;
#pragma unroll
        for (int nf = 0; nf < 8; nf++) {
            s[nf][0] = ex2f(s[nf][0] - mn0);
            s[nf][1] = ex2f(s[nf][1] - mn0);
            s[nf][2] = ex2f(s[nf][2] - mn1);
            s[nf][3] = ex2f(s[nf][3] - mn1);
            sum0 += s[nf][0] + s[nf][1];
            sum1 += s[nf][2] + s[nf][3];
        }
        sum0 += __shfl_xor_sync(0xffffffffu, sum0, 1);
        sum0 += __shfl_xor_sync(0xffffffffu, sum0, 2);
        sum1 += __shfl_xor_sync(0xffffffffu, sum1, 1);
        sum1 += __shfl_xor_sync(0xffffffffu, sum1, 2);

        l[0] = l[0] * al0 + sum0;
        l[1] = l[1] * al1 + sum1;
        m[0] = mn0;
        m[1] = mn1;

#pragma unroll
        for (int d = 0; d < 8; d++) {
            o[d][0] *= al0; o[d][1] *= al0;
            o[d][2] *= al1; o[d][3] *= al1;
        }

        // ---- O += P @ V ----
#pragma unroll
        for (int c = 0; c < 4; c++) {
            uint32_t a0 = pack_h2(s[2*c][0],   s[2*c][1]);
            uint32_t a1 = pack_h2(s[2*c][2],   s[2*c][3]);
            uint32_t a2 = pack_h2(s[2*c+1][0], s[2*c+1][1]);
            uint32_t a3 = pack_h2(s[2*c+1][2], s[2*c+1][3]);
#pragma unroll
            for (int fn2 = 0; fn2 < 4; fn2++) {
                uint32_t vb[4];
                LDSM4(vb, vB + (uint32_t)(fn2 * 16 * FQS) * 2u + c * 32);
                MMA_F16(o[2 * fn2],     a0, a1, a2, a3, vb[0], vb[1]);
                MMA_F16(o[2 * fn2 + 1], a0, a1, a2, a3, vb[2], vb[3]);
            }
        }

        // prefetch kt+2 into stage (kt+2)%3 == (kt-1)%3 (safe: barrier above)
        if (kt + 2 < NT) load_kv(kt + 2, (kt + 2) % KVSTG);
    }

    const float inv0 = 1.f / l[0];
    const float inv1 = 1.f / l[1];
    const int row0 = q0 + m0 + gid;
#pragma unroll
    for (int d = 0; d < 8; d++) {
        const int col = d * 8 + tig * 2;
        *(__half2*)(Ob + (size_t)row0 * DMODEL + col) =
            __floats2half2_rn(o[d][0] * inv0, o[d][1] * inv0);
        *(__half2*)(Ob + (size_t)(row0 + 8) * DMODEL + col) =
            __floats2half2_rn(o[d][2] * inv1, o[d][3] * inv1);
    }
}

// ---------------------------------------------------------------------------
// y = LayerNorm(a + b) * gamma + beta; a fp32, b fp16; dual out (fp32+fp16).
// Shuffle-based reduction (1 barrier).
// ---------------------------------------------------------------------------
__global__ __launch_bounds__(256)
void add_ln2(const float* __restrict__ a, const __half* __restrict__ b,
             const float* __restrict__ gamma, const float* __restrict__ beta,
             float* __restrict__ y, __half* __restrict__ yh)
{
    const int row = blockIdx.x;
    const int tid = threadIdx.x;
    const int wid = tid >> 5;
    const int lid = tid & 31;
    __shared__ float ws[8], wq[8];

    float4 va = ((const float4*)(a + (size_t)row * DMODEL))[tid];
    const __half2* bp = (const __half2*)(b + (size_t)row * DMODEL + tid * 4);
    float2 b01 = __half22float2(bp[0]);
    float2 b23 = __half22float2(bp[1]);
    float s0 = va.x + b01.x, s1 = va.y + b01.y;
    float s2 = va.z + b23.x, s3 = va.w + b23.y;

    float ps = s0 + s1 + s2 + s3;
    float pq = s0 * s0 + s1 * s1 + s2 * s2 + s3 * s3;
#pragma unroll
    for (int off = 16; off > 0; off >>= 1) {
        ps += __shfl_xor_sync(0xffffffffu, ps, off);
        pq += __shfl_xor_sync(0xffffffffu, pq, off);
    }
    if (lid == 0) { ws[wid] = ps; wq[wid] = pq; }
    __syncthreads();
    float ts = 0.f, tq = 0.f;
#pragma unroll
    for (int i = 0; i < 8; i++) { ts += ws[i]; tq += wq[i]; }

    const float mu   = ts * (1.f / DMODEL);
    const float var  = tq * (1.f / DMODEL) - mu * mu;
    const float rinv = rsqrtf(var + 1e-5f);

    float4 g  = ((const float4*)gamma)[tid];
    float4 be = ((const float4*)beta)[tid];
    float4 out;
    out.x = (s0 - mu) * rinv * g.x + be.x;
    out.y = (s1 - mu) * rinv * g.y + be.y;
    out.z = (s2 - mu) * rinv * g.z + be.z;
    out.w = (s3 - mu) * rinv * g.w + be.w;
    ((float4*)(y + (size_t)row * DMODEL))[tid] = out;

    __half* hp = yh + (size_t)row * DMODEL + tid * 4;
    *(__half2*)(hp)     = __floats2half2_rn(out.x, out.y);
    *(__half2*)(hp + 2) = __floats2half2_rn(out.z, out.w);
}

// ---------------------------------------------------------------------------
// launch
// ---------------------------------------------------------------------------
extern "C" void kernel_launch(void* const* d_in, const int* in_sizes, int n_in,
                              void* d_out, int out_size)
{
    const float* x  = (const float*)d_in[0];
    const float* Wq = (const float*)d_in[1];
    const float* Wk = (const float*)d_in[2];
    const float* Wv = (const float*)d_in[3];
    const float* Wo = (const float*)d_in[4];
    const float* W1 = (const float*)d_in[5];
    const float* W2 = (const float*)d_in[6];
    const float* g1 = (const float*)d_in[7];
    const float* b1 = (const float*)d_in[8];
    const float* g2 = (const float*)d_in[9];
    const float* b2 = (const float*)d_in[10];
    float* out = (float*)d_out;

    __half *px, *pwq, *pwk, *pwv, *pwo, *pw1, *pw2;
    __half *pq, *pk, *pvt, *pattn, *px1h, *pff, *pproj;
    float *px1;
    cudaGetSymbolAddress((void**)&px,   hx);
    cudaGetSymbolAddress((void**)&pwq,  hWq);
    cudaGetSymbolAddress((void**)&pwk,  hWk);
    cudaGetSymbolAddress((void**)&pwv,  hWv);
    cudaGetSymbolAddress((void**)&pwo,  hWo);
    cudaGetSymbolAddress((void**)&pw1,  hW1);
    cudaGetSymbolAddress((void**)&pw2,  hW2);
    cudaGetSymbolAddress((void**)&pq,   hq);
    cudaGetSymbolAddress((void**)&pk,   hk);
    cudaGetSymbolAddress((void**)&pvt,  hvt);
    cudaGetSymbolAddress((void**)&pattn,hattn);
    cudaGetSymbolAddress((void**)&px1h, hx1);
    cudaGetSymbolAddress((void**)&pff,  hff);
    cudaGetSymbolAddress((void**)&pproj,hproj);
    cudaGetSymbolAddress((void**)&px1,  g_x1);

    cudaFuncSetAttribute(gemm128<0>, cudaFuncAttributeMaxDynamicSharedMemorySize, GEMM_SMEM);
    cudaFuncSetAttribute(gemm128<3>, cudaFuncAttributeMaxDynamicSharedMemorySize, GEMM_SMEM);
    cudaFuncSetAttribute(gemm_qkv,   cudaFuncAttributeMaxDynamicSharedMemorySize, GEMM_SMEM);
    cudaFuncSetAttribute(flash_h,    cudaFuncAttributeMaxDynamicSharedMemorySize, FLASHH_SMEM);

    dim3 gblk(GTHREADS);
    dim3 blk(256);

    // fp32 -> fp16, single launch
    f2h_all<<<dim3(TOKENS * DMODEL / 1024, 7), blk>>>(
        x, px, Wq, pwq, Wk, pwk, Wv, pwv, Wo, pwo, W1, pw1, W2, pw2);

    // fused QKV projections (grid.x = 3 weights * 8 n-tiles)
    gemm_qkv<<<dim3(24, TOKENS / 128), gblk, GEMM_SMEM>>>(
        px, pwq, pwk, pwv, pq, pk, pvt);

    // attention
    dim3 gattn(SEQ / 128, 2 * NHEADS);
    flash_h<<<gattn, blk, FLASHH_SMEM>>>(pq, pk, pvt, pattn);

    // output projection (fp16) + residual + LN1
    gemm128<0><<<dim3(DMODEL / 128, TOKENS / 128), gblk, GEMM_SMEM>>>(
        pattn, pwo, pproj, TOKENS, DMODEL, DMODEL);
    add_ln2<<<TOKENS, 256>>>(x, pproj, g1, b1, px1, px1h);

    // FF1 (+GELU), FF2 (fp16), residual + LN2
    gemm128<3><<<dim3(DFF / 128, TOKENS / 128), gblk, GEMM_SMEM>>>(
        px1h, pw1, pff, TOKENS, DFF, DMODEL);
    gemm128<0><<<dim3(DMODEL / 128, TOKENS / 128), gblk, GEMM_SMEM>>>(
        pff, pw2, pproj, TOKENS, DMODEL, DFF);
    add_ln2<<<TOKENS, 256>>>(px1, pproj, g2, b2, out, px1h);
}